// round 1
// baseline (speedup 1.0000x reference)
#include <cuda_runtime.h>

#define NSTART 40
#define NOPEN 128
#define NHID 256
#define NCLOSE 3
#define NLAYERS 40
#define NN 1024

// ---------------- device scratch (static, allocation-free) ----------------
__device__ float g_Zc[NOPEN * NN];
__device__ float g_Zold[NOPEN * NN];
__device__ float g_L[NN * NN];
__device__ float g_W2[NN * NN];      // D2, then overwritten by Wg
__device__ float g_deg[NN];
__device__ float g_sq[NN];
__device__ float g_part[256];        // per-block D2 partial sums (deterministic)
__device__ float g_sig;              // sum of D2
__device__ float g_H0[NHID * NN];    // branch0 conv output
__device__ float g_H1[NHID * NN];    // branch1 conv output
__device__ float g_P0[NHID * NN];    // H1 @ L partials (k-halves)
__device__ float g_P1[NHID * NN];
__device__ float g_mean[2 * NHID];
__device__ float g_rstd[2 * NHID];
__device__ float g_T[4][NOPEN * NN]; // convT partials: [b*2 + co_half]
__device__ float g_Q[4][NOPEN * NN]; // T1 @ L partials (k-quarters)

// ---------------- init: Zc = Kopen @ Z ; Zold = Zc ----------------
__global__ void __launch_bounds__(256) k_init(const float* __restrict__ Z,
                                              const float* __restrict__ Kopen) {
    int c = blockIdx.x;  // 0..127
    __shared__ float kr[NSTART];
    if (threadIdx.x < NSTART) kr[threadIdx.x] = Kopen[c * NSTART + threadIdx.x];
    __syncthreads();
    for (int n = threadIdx.x; n < NN; n += 256) {
        float s = 0.f;
#pragma unroll
        for (int k = 0; k < NSTART; k++) s += kr[k] * Z[k * NN + n];
        g_Zc[c * NN + n] = s;
        g_Zold[c * NN + n] = s;
    }
}

// ---------------- Laplacian: sq[n] = sum_c Zc[c,n]^2 ----------------
__global__ void __launch_bounds__(256) k_sq() {
    int n = blockIdx.x * 256 + threadIdx.x;  // grid 4
    float s = 0.f;
#pragma unroll 4
    for (int c = 0; c < NOPEN; c++) {
        float v = g_Zc[c * NN + n];
        s += v * v;
    }
    g_sq[n] = s;
}

// ---------------- Laplacian: D2 tile + per-block partial sum ----------------
__global__ void __launch_bounds__(256) k_d2() {
    const int j0 = blockIdx.x * 64;
    const int i0 = blockIdx.y * 64;
    __shared__ float As[16 * 64];
    __shared__ float Bs[16 * 64];
    __shared__ float red[256];
    const int tid = threadIdx.x;
    const int tj = tid & 15, ti = tid >> 4;
    float acc[4][4] = {};
    for (int c = 0; c < 8; ++c) {
        int k0 = c * 16;
        for (int idx = tid; idx < 1024; idx += 256) {
            int k = idx >> 6, x = idx & 63;
            As[k * 64 + x] = g_Zc[(k0 + k) * NN + i0 + x];
            Bs[k * 64 + x] = g_Zc[(k0 + k) * NN + j0 + x];
        }
        __syncthreads();
#pragma unroll
        for (int kk = 0; kk < 16; ++kk) {
            float4 a = *(const float4*)&As[kk * 64 + ti * 4];
            float4 b = *(const float4*)&Bs[kk * 64 + tj * 4];
            acc[0][0] += a.x * b.x; acc[0][1] += a.x * b.y; acc[0][2] += a.x * b.z; acc[0][3] += a.x * b.w;
            acc[1][0] += a.y * b.x; acc[1][1] += a.y * b.y; acc[1][2] += a.y * b.z; acc[1][3] += a.y * b.w;
            acc[2][0] += a.z * b.x; acc[2][1] += a.z * b.y; acc[2][2] += a.z * b.z; acc[2][3] += a.z * b.w;
            acc[3][0] += a.w * b.x; acc[3][1] += a.w * b.y; acc[3][2] += a.w * b.z; acc[3][3] += a.w * b.w;
        }
        __syncthreads();
    }
    float lsum = 0.f;
#pragma unroll
    for (int r = 0; r < 4; ++r) {
        int i = i0 + ti * 4 + r;
        float sqi = g_sq[i];
        float4 o;
        float* po = (float*)&o;
#pragma unroll
        for (int cc = 0; cc < 4; ++cc) {
            int j = j0 + tj * 4 + cc;
            float d2 = fmaxf(sqi + g_sq[j] - 2.f * acc[r][cc], 0.f);
            po[cc] = d2;
            lsum += d2;
        }
        *(float4*)&g_W2[i * NN + j0 + tj * 4] = o;
    }
    red[tid] = lsum;
    __syncthreads();
    for (int o = 128; o > 0; o >>= 1) {
        if (tid < o) red[tid] += red[tid + o];
        __syncthreads();
    }
    if (tid == 0) g_part[blockIdx.y * 16 + blockIdx.x] = red[0];
}

__global__ void __launch_bounds__(256) k_sigma() {
    __shared__ float red[256];
    red[threadIdx.x] = g_part[threadIdx.x];
    __syncthreads();
    for (int o = 128; o > 0; o >>= 1) {
        if (threadIdx.x < o) red[threadIdx.x] += red[threadIdx.x + o];
        __syncthreads();
    }
    if (threadIdx.x == 0) g_sig = red[0];
}

// ---------------- Laplacian: Wg = exp(-D2/sigma); deg row-sum ----------------
__global__ void __launch_bounds__(256) k_wg() {
    int i = blockIdx.x;  // 1024
    __shared__ float red[256];
    float sigma = g_sig * (1.f / 1048576.f) + 1e-12f;
    float inv = 1.f / sigma;
    float s = 0.f;
    for (int n = threadIdx.x; n < NN; n += 256) {
        float w = expf(-g_W2[i * NN + n] * inv);
        g_W2[i * NN + n] = w;
        s += w;
    }
    red[threadIdx.x] = s;
    __syncthreads();
    for (int o = 128; o > 0; o >>= 1) {
        if (threadIdx.x < o) red[threadIdx.x] += red[threadIdx.x + o];
        __syncthreads();
    }
    if (threadIdx.x == 0) g_deg[i] = red[0];
}

// ---------------- Laplacian: L = I - Dh_i Dh_j Wg (symmetric) ----------------
__global__ void __launch_bounds__(256) k_lap() {
    int i = blockIdx.x;
    float dhi = rsqrtf(g_deg[i]);
    for (int n = threadIdx.x; n < NN; n += 256) {
        float v = -dhi * rsqrtf(g_deg[n]) * g_W2[i * NN + n];
        if (n == i) v += 1.f;
        g_L[i * NN + n] = v;
    }
}

// ---------------- forward conv: H[b] = conv1(Zc + B[b], W[b]) ----------------
__global__ void __launch_bounds__(256) k_conv(const float* __restrict__ W,
                                              const float* __restrict__ Bias, int layer) {
    const int n0 = blockIdx.x * 64;
    const int co0 = blockIdx.y * 64;
    const int b = blockIdx.z;
    const float* Wb = W + ((size_t)(layer * 2 + b) * NHID + co0) * (NOPEN * 9);
    const float* Bb = Bias + (layer * 2 + b) * NOPEN;
    __shared__ float Ws[16 * 9 * 68];
    __shared__ float Xs[16 * 72];
    const int tid = threadIdx.x;
    const int tn = tid & 15, tco = tid >> 4;
    float acc[4][4] = {};
    for (int cc = 0; cc < 8; ++cc) {
        int ci0 = cc * 16;
        for (int idx = tid; idx < 16 * 72; idx += 256) {
            int ci = idx / 72, ml = idx - ci * 72;
            int m = n0 - 4 + ml;
            float v = 0.f;
            if ((unsigned)m < (unsigned)NN) v = g_Zc[(ci0 + ci) * NN + m] + Bb[ci0 + ci];
            Xs[idx] = v;
        }
#pragma unroll
        for (int it = 0; it < 4; ++it) {
            int co = (tid >> 4) + it * 16;
            int ci = tid & 15;
            const float* src = Wb + (co * NOPEN + ci0 + ci) * 9;
            float* dst = &Ws[(ci * 9) * 68 + co];
#pragma unroll
            for (int j = 0; j < 9; ++j) dst[j * 68] = src[j];
        }
        __syncthreads();
#pragma unroll 2
        for (int kk = 0; kk < 16; ++kk) {
            float xw[12];
            float4 x0 = *(const float4*)&Xs[kk * 72 + tn * 4];
            float4 x1 = *(const float4*)&Xs[kk * 72 + tn * 4 + 4];
            float4 x2 = *(const float4*)&Xs[kk * 72 + tn * 4 + 8];
            xw[0] = x0.x; xw[1] = x0.y; xw[2] = x0.z; xw[3] = x0.w;
            xw[4] = x1.x; xw[5] = x1.y; xw[6] = x1.z; xw[7] = x1.w;
            xw[8] = x2.x; xw[9] = x2.y; xw[10] = x2.z; xw[11] = x2.w;
#pragma unroll
            for (int j = 0; j < 9; ++j) {
                float4 w = *(const float4*)&Ws[(kk * 9 + j) * 68 + tco * 4];
#pragma unroll
                for (int nn = 0; nn < 4; ++nn) {
                    float xv = xw[j + nn];
                    acc[0][nn] += w.x * xv;
                    acc[1][nn] += w.y * xv;
                    acc[2][nn] += w.z * xv;
                    acc[3][nn] += w.w * xv;
                }
            }
        }
        __syncthreads();
    }
    float* H = b ? g_H1 : g_H0;
#pragma unroll
    for (int r = 0; r < 4; ++r) {
        float4 o;
        o.x = acc[r][0]; o.y = acc[r][1]; o.z = acc[r][2]; o.w = acc[r][3];
        *(float4*)&H[(co0 + tco * 4 + r) * NN + n0 + tn * 4] = o;
    }
}

// ---------------- GEMM: P[kh] = H1[:, kh*512:+512] @ L[kh*512:+512, :] ----------------
__global__ void __launch_bounds__(256) k_gemmHL() {
    const int n0 = blockIdx.x * 64;
    const int m0 = blockIdx.y * 64;
    const int kh = blockIdx.z;
    const int kbase = kh * 512;
    __shared__ float As[16 * 68];
    __shared__ float Bs[16 * 64];
    const int tid = threadIdx.x;
    const int tn = tid & 15, tm = tid >> 4;
    float acc[4][4] = {};
    for (int c = 0; c < 32; ++c) {
        int k0 = kbase + c * 16;
        for (int idx = tid; idx < 1024; idx += 256) {
            int m = idx >> 4, k = idx & 15;
            As[k * 68 + m] = g_H1[(m0 + m) * NN + k0 + k];
        }
        for (int idx = tid; idx < 1024; idx += 256) {
            int k = idx >> 6, n = idx & 63;
            Bs[k * 64 + n] = g_L[(k0 + k) * NN + n0 + n];
        }
        __syncthreads();
#pragma unroll
        for (int kk = 0; kk < 16; ++kk) {
            float4 a = *(const float4*)&As[kk * 68 + tm * 4];
            float4 b = *(const float4*)&Bs[kk * 64 + tn * 4];
            acc[0][0] += a.x * b.x; acc[0][1] += a.x * b.y; acc[0][2] += a.x * b.z; acc[0][3] += a.x * b.w;
            acc[1][0] += a.y * b.x; acc[1][1] += a.y * b.y; acc[1][2] += a.y * b.z; acc[1][3] += a.y * b.w;
            acc[2][0] += a.z * b.x; acc[2][1] += a.z * b.y; acc[2][2] += a.z * b.z; acc[2][3] += a.z * b.w;
            acc[3][0] += a.w * b.x; acc[3][1] += a.w * b.y; acc[3][2] += a.w * b.z; acc[3][3] += a.w * b.w;
        }
        __syncthreads();
    }
    float* P = kh ? g_P1 : g_P0;
#pragma unroll
    for (int r = 0; r < 4; ++r) {
        float4 o;
        o.x = acc[r][0]; o.y = acc[r][1]; o.z = acc[r][2]; o.w = acc[r][3];
        *(float4*)&P[(m0 + tm * 4 + r) * NN + n0 + tn * 4] = o;
    }
}

// ---------------- instance-norm stats per channel ----------------
__global__ void __launch_bounds__(256) k_stats() {
    int ch = blockIdx.x;  // 512
    int b = ch >> 8, c = ch & 255;
    __shared__ float rs[256], rs2[256];
    float s = 0.f, s2 = 0.f;
    if (b == 0) {
        const float* p = &g_H0[c * NN];
        for (int n = threadIdx.x; n < NN; n += 256) {
            float v = p[n];
            s += v; s2 += v * v;
        }
    } else {
        const float* p0 = &g_P0[c * NN];
        const float* p1 = &g_P1[c * NN];
        for (int n = threadIdx.x; n < NN; n += 256) {
            float v = p0[n] + p1[n];
            s += v; s2 += v * v;
        }
    }
    rs[threadIdx.x] = s; rs2[threadIdx.x] = s2;
    __syncthreads();
    for (int o = 128; o > 0; o >>= 1) {
        if (threadIdx.x < o) { rs[threadIdx.x] += rs[threadIdx.x + o]; rs2[threadIdx.x] += rs2[threadIdx.x + o]; }
        __syncthreads();
    }
    if (threadIdx.x == 0) {
        float mean = rs[0] * (1.f / NN);
        float var = rs2[0] * (1.f / NN) - mean * mean;
        g_mean[ch] = mean;
        g_rstd[ch] = rsqrtf(var + 1e-5f);
    }
}

// ---------------- transposed conv (fused norm+relu on input), k-split over co ----------------
__global__ void __launch_bounds__(256) k_convT(const float* __restrict__ W, int layer) {
    const int n0 = blockIdx.x * 64;
    const int ci0 = blockIdx.y * 64;
    const int b = blockIdx.z >> 1;
    const int hf = blockIdx.z & 1;
    const float* Wb = W + (size_t)(layer * 2 + b) * NHID * NOPEN * 9;
    __shared__ float Ws[16 * 9 * 68];
    __shared__ float Ys[16 * 72];
    const int tid = threadIdx.x;
    const int tn = tid & 15, tci = tid >> 4;
    float acc[4][4] = {};
    for (int cc = 0; cc < 8; ++cc) {
        int cb = hf * 128 + cc * 16;
        for (int idx = tid; idx < 16 * 72; idx += 256) {
            int col = idx / 72, ml = idx - col * 72;
            int co = cb + col;
            int m = n0 - 4 + ml;
            float v = 0.f;
            if ((unsigned)m < (unsigned)NN) {
                float sv = b ? (g_P0[co * NN + m] + g_P1[co * NN + m]) : g_H0[co * NN + m];
                v = fmaxf((sv - g_mean[b * 256 + co]) * g_rstd[b * 256 + co], 0.f);
            }
            Ys[idx] = v;
        }
#pragma unroll
        for (int it = 0; it < 4; ++it) {
            int col = (tid >> 6) + it * 4;  // 0..15 (co within chunk)
            int cil = tid & 63;
            const float* src = Wb + ((cb + col) * NOPEN + ci0 + cil) * 9;
            float* dst = &Ws[(col * 9) * 68 + cil];
#pragma unroll
            for (int j = 0; j < 9; ++j) dst[j * 68] = src[j];
        }
        __syncthreads();
#pragma unroll 2
        for (int kk = 0; kk < 16; ++kk) {
            float yw[12];
            float4 y0 = *(const float4*)&Ys[kk * 72 + tn * 4];
            float4 y1 = *(const float4*)&Ys[kk * 72 + tn * 4 + 4];
            float4 y2 = *(const float4*)&Ys[kk * 72 + tn * 4 + 8];
            yw[0] = y0.x; yw[1] = y0.y; yw[2] = y0.z; yw[3] = y0.w;
            yw[4] = y1.x; yw[5] = y1.y; yw[6] = y1.z; yw[7] = y1.w;
            yw[8] = y2.x; yw[9] = y2.y; yw[10] = y2.z; yw[11] = y2.w;
#pragma unroll
            for (int j = 0; j < 9; ++j) {
                float4 w = *(const float4*)&Ws[(kk * 9 + j) * 68 + tci * 4];
#pragma unroll
                for (int nn = 0; nn < 4; ++nn) {
                    float yv = yw[(8 - j) + nn];  // Y[co, n + 4 - j]
                    acc[0][nn] += w.x * yv;
                    acc[1][nn] += w.y * yv;
                    acc[2][nn] += w.z * yv;
                    acc[3][nn] += w.w * yv;
                }
            }
        }
        __syncthreads();
    }
    float* T = g_T[b * 2 + hf];
#pragma unroll
    for (int r = 0; r < 4; ++r) {
        float4 o;
        o.x = acc[r][0]; o.y = acc[r][1]; o.z = acc[r][2]; o.w = acc[r][3];
        *(float4*)&T[(ci0 + tci * 4 + r) * NN + n0 + tn * 4] = o;
    }
}

// ---------------- GEMM: Q[kq] = (T1a+T1b)[:, kq*256:+256] @ L[kq*256:+256, :] ----------------
__global__ void __launch_bounds__(256) k_gemmQ() {
    const int n0 = blockIdx.x * 64;
    const int m0 = blockIdx.y * 64;
    const int kq = blockIdx.z;
    const int kbase = kq * 256;
    __shared__ float As[16 * 68];
    __shared__ float Bs[16 * 64];
    const int tid = threadIdx.x;
    const int tn = tid & 15, tm = tid >> 4;
    float acc[4][4] = {};
    for (int c = 0; c < 16; ++c) {
        int k0 = kbase + c * 16;
        for (int idx = tid; idx < 1024; idx += 256) {
            int m = idx >> 4, k = idx & 15;
            int off = (m0 + m) * NN + k0 + k;
            As[k * 68 + m] = g_T[2][off] + g_T[3][off];
        }
        for (int idx = tid; idx < 1024; idx += 256) {
            int k = idx >> 6, n = idx & 63;
            Bs[k * 64 + n] = g_L[(k0 + k) * NN + n0 + n];
        }
        __syncthreads();
#pragma unroll
        for (int kk = 0; kk < 16; ++kk) {
            float4 a = *(const float4*)&As[kk * 68 + tm * 4];
            float4 b = *(const float4*)&Bs[kk * 64 + tn * 4];
            acc[0][0] += a.x * b.x; acc[0][1] += a.x * b.y; acc[0][2] += a.x * b.z; acc[0][3] += a.x * b.w;
            acc[1][0] += a.y * b.x; acc[1][1] += a.y * b.y; acc[1][2] += a.y * b.z; acc[1][3] += a.y * b.w;
            acc[2][0] += a.z * b.x; acc[2][1] += a.z * b.y; acc[2][2] += a.z * b.z; acc[2][3] += a.z * b.w;
            acc[3][0] += a.w * b.x; acc[3][1] += a.w * b.y; acc[3][2] += a.w * b.z; acc[3][3] += a.w * b.w;
        }
        __syncthreads();
    }
    float* Q = g_Q[kq];
#pragma unroll
    for (int r = 0; r < 4; ++r) {
        float4 o;
        o.x = acc[r][0]; o.y = acc[r][1]; o.z = acc[r][2]; o.w = acc[r][3];
        *(float4*)&Q[(m0 + tm * 4 + r) * NN + n0 + tn * 4] = o;
    }
}

// ---------------- leapfrog update ----------------
__global__ void __launch_bounds__(256) k_update() {
    int base = (blockIdx.x * 256 + threadIdx.x) * 4;  // grid 128
    float4 q0 = *(const float4*)&g_Q[0][base];
    float4 q1 = *(const float4*)&g_Q[1][base];
    float4 q2 = *(const float4*)&g_Q[2][base];
    float4 q3 = *(const float4*)&g_Q[3][base];
    float4 t0 = *(const float4*)&g_T[0][base];
    float4 t1 = *(const float4*)&g_T[1][base];
    float4 zc = *(const float4*)&g_Zc[base];
    float4 zo = *(const float4*)&g_Zold[base];
    float4 zn;
    zn.x = 2.f * zc.x - zo.x - 0.01f * (t0.x + t1.x + q0.x + q1.x + q2.x + q3.x);
    zn.y = 2.f * zc.y - zo.y - 0.01f * (t0.y + t1.y + q0.y + q1.y + q2.y + q3.y);
    zn.z = 2.f * zc.z - zo.z - 0.01f * (t0.z + t1.z + q0.z + q1.z + q2.z + q3.z);
    zn.w = 2.f * zc.w - zo.w - 0.01f * (t0.w + t1.w + q0.w + q1.w + q2.w + q3.w);
    *(float4*)&g_Zold[base] = zc;
    *(float4*)&g_Zc[base] = zn;
}

// ---------------- output: [Kclose@Zc ; Kclose@Zold] ----------------
__global__ void __launch_bounds__(256) k_out(const float* __restrict__ Kclose,
                                             float* __restrict__ out) {
    int r = blockIdx.x % 3, sel = blockIdx.x / 3;  // grid 6
    const float* src = sel ? g_Zold : g_Zc;
    __shared__ float kc[NOPEN];
    if (threadIdx.x < NOPEN) kc[threadIdx.x] = Kclose[r * NOPEN + threadIdx.x];
    __syncthreads();
    for (int n = threadIdx.x; n < NN; n += 256) {
        float s = 0.f;
#pragma unroll 8
        for (int k = 0; k < NOPEN; k++) s += kc[k] * src[k * NN + n];
        out[sel * (NCLOSE * NN) + r * NN + n] = s;
    }
}

// ---------------- host ----------------
extern "C" void kernel_launch(void* const* d_in, const int* in_sizes, int n_in,
                              void* d_out, int out_size) {
    const float* Z      = (const float*)d_in[0];
    const float* Kopen  = (const float*)d_in[1];
    const float* Kclose = (const float*)d_in[2];
    const float* W      = (const float*)d_in[3];
    const float* Bias   = (const float*)d_in[4];
    float* out = (float*)d_out;

    k_init<<<128, 256>>>(Z, Kopen);
    for (int i = 0; i < NLAYERS; i++) {
        if (i % 10 == 0) {
            k_sq<<<4, 256>>>();
            k_d2<<<dim3(16, 16), 256>>>();
            k_sigma<<<1, 256>>>();
            k_wg<<<1024, 256>>>();
            k_lap<<<1024, 256>>>();
        }
        k_conv<<<dim3(16, 4, 2), 256>>>(W, Bias, i);
        k_gemmHL<<<dim3(16, 4, 2), 256>>>();
        k_stats<<<512, 256>>>();
        k_convT<<<dim3(16, 2, 4), 256>>>(W, i);
        k_gemmQ<<<dim3(16, 2, 4), 256>>>();
        k_update<<<128, 256>>>();
    }
    k_out<<<6, 256>>>(Kclose, out);
}

// round 2
// speedup vs baseline: 1.0008x; 1.0008x over previous
#include <cuda_runtime.h>

#define NSTART 40
#define NOPEN 128
#define NHID 256
#define NCLOSE 3
#define NLAYERS 40
#define NN 1024

// ---------------- device scratch (static, allocation-free) ----------------
__device__ float g_Zc[NOPEN * NN];
__device__ float g_Zold[NOPEN * NN];
__device__ float g_L[NN * NN];
__device__ float g_W2[NN * NN];      // D2, then overwritten by Wg
__device__ float g_deg[NN];
__device__ float g_sq[NN];
__device__ float g_part[256];        // per-block D2 partial sums (deterministic)
__device__ float g_sig;              // sum of D2
__device__ float g_H0[NHID * NN];    // branch0 conv output
__device__ float g_H1[NHID * NN];    // branch1 conv output
__device__ float g_P0[NHID * NN];    // H1 @ L partials (k-halves)
__device__ float g_P1[NHID * NN];
__device__ float g_mean[2 * NHID];
__device__ float g_rstd[2 * NHID];
__device__ float g_T[4][NOPEN * NN]; // convT partials: [b*2 + co_half]
__device__ float g_Q[4][NOPEN * NN]; // T1 @ L partials (k-quarters)

// ---------------- init: Zc = Kopen @ Z ; Zold = Zc ----------------
__global__ void __launch_bounds__(256) k_init(const float* __restrict__ Z,
                                              const float* __restrict__ Kopen) {
    int c = blockIdx.x;  // 0..127
    __shared__ float kr[NSTART];
    if (threadIdx.x < NSTART) kr[threadIdx.x] = Kopen[c * NSTART + threadIdx.x];
    __syncthreads();
    for (int n = threadIdx.x; n < NN; n += 256) {
        float s = 0.f;
#pragma unroll
        for (int k = 0; k < NSTART; k++) s += kr[k] * Z[k * NN + n];
        g_Zc[c * NN + n] = s;
        g_Zold[c * NN + n] = s;
    }
}

// ---------------- Laplacian: sq[n] = sum_c Zc[c,n]^2 ----------------
__global__ void __launch_bounds__(256) k_sq() {
    int n = blockIdx.x * 256 + threadIdx.x;  // grid 4
    float s = 0.f;
#pragma unroll 4
    for (int c = 0; c < NOPEN; c++) {
        float v = g_Zc[c * NN + n];
        s += v * v;
    }
    g_sq[n] = s;
}

// ---------------- Laplacian: D2 tile + per-block partial sum ----------------
__global__ void __launch_bounds__(256) k_d2() {
    const int j0 = blockIdx.x * 64;
    const int i0 = blockIdx.y * 64;
    __shared__ float As[16 * 64];
    __shared__ float Bs[16 * 64];
    __shared__ float red[256];
    const int tid = threadIdx.x;
    const int tj = tid & 15, ti = tid >> 4;
    float acc[4][4] = {};
    for (int c = 0; c < 8; ++c) {
        int k0 = c * 16;
        for (int idx = tid; idx < 1024; idx += 256) {
            int k = idx >> 6, x = idx & 63;
            As[k * 64 + x] = g_Zc[(k0 + k) * NN + i0 + x];
            Bs[k * 64 + x] = g_Zc[(k0 + k) * NN + j0 + x];
        }
        __syncthreads();
#pragma unroll
        for (int kk = 0; kk < 16; ++kk) {
            float4 a = *(const float4*)&As[kk * 64 + ti * 4];
            float4 b = *(const float4*)&Bs[kk * 64 + tj * 4];
            acc[0][0] += a.x * b.x; acc[0][1] += a.x * b.y; acc[0][2] += a.x * b.z; acc[0][3] += a.x * b.w;
            acc[1][0] += a.y * b.x; acc[1][1] += a.y * b.y; acc[1][2] += a.y * b.z; acc[1][3] += a.y * b.w;
            acc[2][0] += a.z * b.x; acc[2][1] += a.z * b.y; acc[2][2] += a.z * b.z; acc[2][3] += a.z * b.w;
            acc[3][0] += a.w * b.x; acc[3][1] += a.w * b.y; acc[3][2] += a.w * b.z; acc[3][3] += a.w * b.w;
        }
        __syncthreads();
    }
    float lsum = 0.f;
#pragma unroll
    for (int r = 0; r < 4; ++r) {
        int i = i0 + ti * 4 + r;
        float sqi = g_sq[i];
        float4 o;
        float* po = (float*)&o;
#pragma unroll
        for (int cc = 0; cc < 4; ++cc) {
            int j = j0 + tj * 4 + cc;
            float d2 = fmaxf(sqi + g_sq[j] - 2.f * acc[r][cc], 0.f);
            po[cc] = d2;
            lsum += d2;
        }
        *(float4*)&g_W2[i * NN + j0 + tj * 4] = o;
    }
    red[tid] = lsum;
    __syncthreads();
    for (int o = 128; o > 0; o >>= 1) {
        if (tid < o) red[tid] += red[tid + o];
        __syncthreads();
    }
    if (tid == 0) g_part[blockIdx.y * 16 + blockIdx.x] = red[0];
}

__global__ void __launch_bounds__(256) k_sigma() {
    __shared__ float red[256];
    red[threadIdx.x] = g_part[threadIdx.x];
    __syncthreads();
    for (int o = 128; o > 0; o >>= 1) {
        if (threadIdx.x < o) red[threadIdx.x] += red[threadIdx.x + o];
        __syncthreads();
    }
    if (threadIdx.x == 0) g_sig = red[0];
}

// ---------------- Laplacian: Wg = exp(-D2/sigma); deg row-sum ----------------
__global__ void __launch_bounds__(256) k_wg() {
    int i = blockIdx.x;  // 1024
    __shared__ float red[256];
    float sigma = g_sig * (1.f / 1048576.f) + 1e-12f;
    float inv = 1.f / sigma;
    float s = 0.f;
    for (int n = threadIdx.x; n < NN; n += 256) {
        float w = expf(-g_W2[i * NN + n] * inv);
        g_W2[i * NN + n] = w;
        s += w;
    }
    red[threadIdx.x] = s;
    __syncthreads();
    for (int o = 128; o > 0; o >>= 1) {
        if (threadIdx.x < o) red[threadIdx.x] += red[threadIdx.x + o];
        __syncthreads();
    }
    if (threadIdx.x == 0) g_deg[i] = red[0];
}

// ---------------- Laplacian: L = I - Dh_i Dh_j Wg (symmetric) ----------------
__global__ void __launch_bounds__(256) k_lap() {
    int i = blockIdx.x;
    float dhi = rsqrtf(g_deg[i]);
    for (int n = threadIdx.x; n < NN; n += 256) {
        float v = -dhi * rsqrtf(g_deg[n]) * g_W2[i * NN + n];
        if (n == i) v += 1.f;
        g_L[i * NN + n] = v;
    }
}

// ---------------- forward conv: H[b] = conv1(Zc + B[b], W[b]) ----------------
__global__ void __launch_bounds__(256) k_conv(const float* __restrict__ W,
                                              const float* __restrict__ Bias, int layer) {
    const int n0 = blockIdx.x * 64;
    const int co0 = blockIdx.y * 64;
    const int b = blockIdx.z;
    const float* Wb = W + ((size_t)(layer * 2 + b) * NHID + co0) * (NOPEN * 9);
    const float* Bb = Bias + (layer * 2 + b) * NOPEN;
    __shared__ float Ws[16 * 9 * 68];
    __shared__ float Xs[16 * 72];
    const int tid = threadIdx.x;
    const int tn = tid & 15, tco = tid >> 4;
    float acc[4][4] = {};
    for (int cc = 0; cc < 8; ++cc) {
        int ci0 = cc * 16;
        for (int idx = tid; idx < 16 * 72; idx += 256) {
            int ci = idx / 72, ml = idx - ci * 72;
            int m = n0 - 4 + ml;
            float v = 0.f;
            if ((unsigned)m < (unsigned)NN) v = g_Zc[(ci0 + ci) * NN + m] + Bb[ci0 + ci];
            Xs[idx] = v;
        }
#pragma unroll
        for (int it = 0; it < 4; ++it) {
            int co = (tid >> 4) + it * 16;
            int ci = tid & 15;
            const float* src = Wb + (co * NOPEN + ci0 + ci) * 9;
            float* dst = &Ws[(ci * 9) * 68 + co];
#pragma unroll
            for (int j = 0; j < 9; ++j) dst[j * 68] = src[j];
        }
        __syncthreads();
#pragma unroll 2
        for (int kk = 0; kk < 16; ++kk) {
            float xw[12];
            float4 x0 = *(const float4*)&Xs[kk * 72 + tn * 4];
            float4 x1 = *(const float4*)&Xs[kk * 72 + tn * 4 + 4];
            float4 x2 = *(const float4*)&Xs[kk * 72 + tn * 4 + 8];
            xw[0] = x0.x; xw[1] = x0.y; xw[2] = x0.z; xw[3] = x0.w;
            xw[4] = x1.x; xw[5] = x1.y; xw[6] = x1.z; xw[7] = x1.w;
            xw[8] = x2.x; xw[9] = x2.y; xw[10] = x2.z; xw[11] = x2.w;
#pragma unroll
            for (int j = 0; j < 9; ++j) {
                float4 w = *(const float4*)&Ws[(kk * 9 + j) * 68 + tco * 4];
#pragma unroll
                for (int nn = 0; nn < 4; ++nn) {
                    float xv = xw[j + nn];
                    acc[0][nn] += w.x * xv;
                    acc[1][nn] += w.y * xv;
                    acc[2][nn] += w.z * xv;
                    acc[3][nn] += w.w * xv;
                }
            }
        }
        __syncthreads();
    }
    float* H = b ? g_H1 : g_H0;
#pragma unroll
    for (int r = 0; r < 4; ++r) {
        float4 o;
        o.x = acc[r][0]; o.y = acc[r][1]; o.z = acc[r][2]; o.w = acc[r][3];
        *(float4*)&H[(co0 + tco * 4 + r) * NN + n0 + tn * 4] = o;
    }
}

// ---------------- GEMM: P[kh] = H1[:, kh*512:+512] @ L[kh*512:+512, :] ----------------
__global__ void __launch_bounds__(256) k_gemmHL() {
    const int n0 = blockIdx.x * 64;
    const int m0 = blockIdx.y * 64;
    const int kh = blockIdx.z;
    const int kbase = kh * 512;
    __shared__ float As[16 * 68];
    __shared__ float Bs[16 * 64];
    const int tid = threadIdx.x;
    const int tn = tid & 15, tm = tid >> 4;
    float acc[4][4] = {};
    for (int c = 0; c < 32; ++c) {
        int k0 = kbase + c * 16;
        for (int idx = tid; idx < 1024; idx += 256) {
            int m = idx >> 4, k = idx & 15;
            As[k * 68 + m] = g_H1[(m0 + m) * NN + k0 + k];
        }
        for (int idx = tid; idx < 1024; idx += 256) {
            int k = idx >> 6, n = idx & 63;
            Bs[k * 64 + n] = g_L[(k0 + k) * NN + n0 + n];
        }
        __syncthreads();
#pragma unroll
        for (int kk = 0; kk < 16; ++kk) {
            float4 a = *(const float4*)&As[kk * 68 + tm * 4];
            float4 b = *(const float4*)&Bs[kk * 64 + tn * 4];
            acc[0][0] += a.x * b.x; acc[0][1] += a.x * b.y; acc[0][2] += a.x * b.z; acc[0][3] += a.x * b.w;
            acc[1][0] += a.y * b.x; acc[1][1] += a.y * b.y; acc[1][2] += a.y * b.z; acc[1][3] += a.y * b.w;
            acc[2][0] += a.z * b.x; acc[2][1] += a.z * b.y; acc[2][2] += a.z * b.z; acc[2][3] += a.z * b.w;
            acc[3][0] += a.w * b.x; acc[3][1] += a.w * b.y; acc[3][2] += a.w * b.z; acc[3][3] += a.w * b.w;
        }
        __syncthreads();
    }
    float* P = kh ? g_P1 : g_P0;
#pragma unroll
    for (int r = 0; r < 4; ++r) {
        float4 o;
        o.x = acc[r][0]; o.y = acc[r][1]; o.z = acc[r][2]; o.w = acc[r][3];
        *(float4*)&P[(m0 + tm * 4 + r) * NN + n0 + tn * 4] = o;
    }
}

// ---------------- instance-norm stats per channel ----------------
__global__ void __launch_bounds__(256) k_stats() {
    int ch = blockIdx.x;  // 512
    int b = ch >> 8, c = ch & 255;
    __shared__ float rs[256], rs2[256];
    float s = 0.f, s2 = 0.f;
    if (b == 0) {
        const float* p = &g_H0[c * NN];
        for (int n = threadIdx.x; n < NN; n += 256) {
            float v = p[n];
            s += v; s2 += v * v;
        }
    } else {
        const float* p0 = &g_P0[c * NN];
        const float* p1 = &g_P1[c * NN];
        for (int n = threadIdx.x; n < NN; n += 256) {
            float v = p0[n] + p1[n];
            s += v; s2 += v * v;
        }
    }
    rs[threadIdx.x] = s; rs2[threadIdx.x] = s2;
    __syncthreads();
    for (int o = 128; o > 0; o >>= 1) {
        if (threadIdx.x < o) { rs[threadIdx.x] += rs[threadIdx.x + o]; rs2[threadIdx.x] += rs2[threadIdx.x + o]; }
        __syncthreads();
    }
    if (threadIdx.x == 0) {
        float mean = rs[0] * (1.f / NN);
        float var = rs2[0] * (1.f / NN) - mean * mean;
        g_mean[ch] = mean;
        g_rstd[ch] = rsqrtf(var + 1e-5f);
    }
}

// ---------------- transposed conv (fused norm+relu on input), k-split over co ----------------
__global__ void __launch_bounds__(256) k_convT(const float* __restrict__ W, int layer) {
    const int n0 = blockIdx.x * 64;
    const int ci0 = blockIdx.y * 64;
    const int b = blockIdx.z >> 1;
    const int hf = blockIdx.z & 1;
    const float* Wb = W + (size_t)(layer * 2 + b) * NHID * NOPEN * 9;
    __shared__ float Ws[16 * 9 * 68];
    __shared__ float Ys[16 * 72];
    const int tid = threadIdx.x;
    const int tn = tid & 15, tci = tid >> 4;
    float acc[4][4] = {};
    for (int cc = 0; cc < 8; ++cc) {
        int cb = hf * 128 + cc * 16;
        for (int idx = tid; idx < 16 * 72; idx += 256) {
            int col = idx / 72, ml = idx - col * 72;
            int co = cb + col;
            int m = n0 - 4 + ml;
            float v = 0.f;
            if ((unsigned)m < (unsigned)NN) {
                float sv = b ? (g_P0[co * NN + m] + g_P1[co * NN + m]) : g_H0[co * NN + m];
                v = fmaxf((sv - g_mean[b * 256 + co]) * g_rstd[b * 256 + co], 0.f);
            }
            Ys[idx] = v;
        }
#pragma unroll
        for (int it = 0; it < 4; ++it) {
            int col = (tid >> 6) + it * 4;  // 0..15 (co within chunk)
            int cil = tid & 63;
            const float* src = Wb + ((cb + col) * NOPEN + ci0 + cil) * 9;
            float* dst = &Ws[(col * 9) * 68 + cil];
#pragma unroll
            for (int j = 0; j < 9; ++j) dst[j * 68] = src[j];
        }
        __syncthreads();
#pragma unroll 2
        for (int kk = 0; kk < 16; ++kk) {
            float yw[12];
            float4 y0 = *(const float4*)&Ys[kk * 72 + tn * 4];
            float4 y1 = *(const float4*)&Ys[kk * 72 + tn * 4 + 4];
            float4 y2 = *(const float4*)&Ys[kk * 72 + tn * 4 + 8];
            yw[0] = y0.x; yw[1] = y0.y; yw[2] = y0.z; yw[3] = y0.w;
            yw[4] = y1.x; yw[5] = y1.y; yw[6] = y1.z; yw[7] = y1.w;
            yw[8] = y2.x; yw[9] = y2.y; yw[10] = y2.z; yw[11] = y2.w;
#pragma unroll
            for (int j = 0; j < 9; ++j) {
                float4 w = *(const float4*)&Ws[(kk * 9 + j) * 68 + tci * 4];
#pragma unroll
                for (int nn = 0; nn < 4; ++nn) {
                    float yv = yw[(8 - j) + nn];  // Y[co, n + 4 - j]
                    acc[0][nn] += w.x * yv;
                    acc[1][nn] += w.y * yv;
                    acc[2][nn] += w.z * yv;
                    acc[3][nn] += w.w * yv;
                }
            }
        }
        __syncthreads();
    }
    float* T = g_T[b * 2 + hf];
#pragma unroll
    for (int r = 0; r < 4; ++r) {
        float4 o;
        o.x = acc[r][0]; o.y = acc[r][1]; o.z = acc[r][2]; o.w = acc[r][3];
        *(float4*)&T[(ci0 + tci * 4 + r) * NN + n0 + tn * 4] = o;
    }
}

// ---------------- GEMM: Q[kq] = (T1a+T1b)[:, kq*256:+256] @ L[kq*256:+256, :] ----------------
__global__ void __launch_bounds__(256) k_gemmQ() {
    const int n0 = blockIdx.x * 64;
    const int m0 = blockIdx.y * 64;
    const int kq = blockIdx.z;
    const int kbase = kq * 256;
    __shared__ float As[16 * 68];
    __shared__ float Bs[16 * 64];
    const int tid = threadIdx.x;
    const int tn = tid & 15, tm = tid >> 4;
    float acc[4][4] = {};
    for (int c = 0; c < 16; ++c) {
        int k0 = kbase + c * 16;
        for (int idx = tid; idx < 1024; idx += 256) {
            int m = idx >> 4, k = idx & 15;
            int off = (m0 + m) * NN + k0 + k;
            As[k * 68 + m] = g_T[2][off] + g_T[3][off];
        }
        for (int idx = tid; idx < 1024; idx += 256) {
            int k = idx >> 6, n = idx & 63;
            Bs[k * 64 + n] = g_L[(k0 + k) * NN + n0 + n];
        }
        __syncthreads();
#pragma unroll
        for (int kk = 0; kk < 16; ++kk) {
            float4 a = *(const float4*)&As[kk * 68 + tm * 4];
            float4 b = *(const float4*)&Bs[kk * 64 + tn * 4];
            acc[0][0] += a.x * b.x; acc[0][1] += a.x * b.y; acc[0][2] += a.x * b.z; acc[0][3] += a.x * b.w;
            acc[1][0] += a.y * b.x; acc[1][1] += a.y * b.y; acc[1][2] += a.y * b.z; acc[1][3] += a.y * b.w;
            acc[2][0] += a.z * b.x; acc[2][1] += a.z * b.y; acc[2][2] += a.z * b.z; acc[2][3] += a.z * b.w;
            acc[3][0] += a.w * b.x; acc[3][1] += a.w * b.y; acc[3][2] += a.w * b.z; acc[3][3] += a.w * b.w;
        }
        __syncthreads();
    }
    float* Q = g_Q[kq];
#pragma unroll
    for (int r = 0; r < 4; ++r) {
        float4 o;
        o.x = acc[r][0]; o.y = acc[r][1]; o.z = acc[r][2]; o.w = acc[r][3];
        *(float4*)&Q[(m0 + tm * 4 + r) * NN + n0 + tn * 4] = o;
    }
}

// ---------------- leapfrog update ----------------
__global__ void __launch_bounds__(256) k_update() {
    int base = (blockIdx.x * 256 + threadIdx.x) * 4;  // grid 128
    float4 q0 = *(const float4*)&g_Q[0][base];
    float4 q1 = *(const float4*)&g_Q[1][base];
    float4 q2 = *(const float4*)&g_Q[2][base];
    float4 q3 = *(const float4*)&g_Q[3][base];
    float4 t0 = *(const float4*)&g_T[0][base];
    float4 t1 = *(const float4*)&g_T[1][base];
    float4 zc = *(const float4*)&g_Zc[base];
    float4 zo = *(const float4*)&g_Zold[base];
    float4 zn;
    zn.x = 2.f * zc.x - zo.x - 0.01f * (t0.x + t1.x + q0.x + q1.x + q2.x + q3.x);
    zn.y = 2.f * zc.y - zo.y - 0.01f * (t0.y + t1.y + q0.y + q1.y + q2.y + q3.y);
    zn.z = 2.f * zc.z - zo.z - 0.01f * (t0.z + t1.z + q0.z + q1.z + q2.z + q3.z);
    zn.w = 2.f * zc.w - zo.w - 0.01f * (t0.w + t1.w + q0.w + q1.w + q2.w + q3.w);
    *(float4*)&g_Zold[base] = zc;
    *(float4*)&g_Zc[base] = zn;
}

// ---------------- output: [Kclose@Zc ; Kclose@Zold] ----------------
__global__ void __launch_bounds__(256) k_out(const float* __restrict__ Kclose,
                                             float* __restrict__ out) {
    int r = blockIdx.x % 3, sel = blockIdx.x / 3;  // grid 6
    const float* src = sel ? g_Zold : g_Zc;
    __shared__ float kc[NOPEN];
    if (threadIdx.x < NOPEN) kc[threadIdx.x] = Kclose[r * NOPEN + threadIdx.x];
    __syncthreads();
    for (int n = threadIdx.x; n < NN; n += 256) {
        float s = 0.f;
#pragma unroll 8
        for (int k = 0; k < NOPEN; k++) s += kc[k] * src[k * NN + n];
        out[sel * (NCLOSE * NN) + r * NN + n] = s;
    }
}

// ---------------- host ----------------
extern "C" void kernel_launch(void* const* d_in, const int* in_sizes, int n_in,
                              void* d_out, int out_size) {
    const float* Z      = (const float*)d_in[0];
    const float* Kopen  = (const float*)d_in[1];
    const float* Kclose = (const float*)d_in[2];
    const float* W      = (const float*)d_in[3];
    const float* Bias   = (const float*)d_in[4];
    float* out = (float*)d_out;

    k_init<<<128, 256>>>(Z, Kopen);
    for (int i = 0; i < NLAYERS; i++) {
        if (i % 10 == 0) {
            k_sq<<<4, 256>>>();
            k_d2<<<dim3(16, 16), 256>>>();
            k_sigma<<<1, 256>>>();
            k_wg<<<1024, 256>>>();
            k_lap<<<1024, 256>>>();
        }
        k_conv<<<dim3(16, 4, 2), 256>>>(W, Bias, i);
        k_gemmHL<<<dim3(16, 4, 2), 256>>>();
        k_stats<<<512, 256>>>();
        k_convT<<<dim3(16, 2, 4), 256>>>(W, i);
        k_gemmQ<<<dim3(16, 2, 4), 256>>>();
        k_update<<<128, 256>>>();
    }
    k_out<<<6, 256>>>(Kclose, out);
}

// round 3
// speedup vs baseline: 1.1663x; 1.1654x over previous
#include <cuda_runtime.h>
#include <cstdint>

#define NSTART 40
#define NOPEN 128
#define NHID 256
#define NCLOSE 3
#define NLAYERS 40
#define NN 1024

// ---------------- device scratch (static, allocation-free) ----------------
__device__ float g_Zc[NOPEN * NN];
__device__ float g_Zold[NOPEN * NN];
__device__ float g_L[NN * NN];
__device__ uint32_t g_Lfm[NN * NN];  // L in fragment-major tf32
__device__ float g_W2[NN * NN];
__device__ float g_deg[NN];
__device__ float g_sq[NN];
__device__ float g_part[256];
__device__ float g_sig;
__device__ float g_H0[NHID * NN];
__device__ float g_H1[NHID * NN];
__device__ float g_P0[NHID * NN];
__device__ float g_P1[NHID * NN];
__device__ float g_mean[2 * NHID];
__device__ float g_rstd[2 * NHID];
__device__ float g_T[4][NOPEN * NN];
__device__ float g_Q[4][NOPEN * NN];

// ---------------- mma helpers ----------------
__device__ __forceinline__ uint32_t f2t(float x) {
    uint32_t r;
    asm("cvt.rna.tf32.f32 %0, %1;" : "=r"(r) : "f"(x));
    return r;
}
__device__ __forceinline__ void mma8(float* d, const uint32_t* a, const uint32_t* b) {
    asm volatile(
        "mma.sync.aligned.m16n8k8.row.col.f32.tf32.tf32.f32 "
        "{%0,%1,%2,%3}, {%4,%5,%6,%7}, {%8,%9}, {%0,%1,%2,%3};"
        : "+f"(d[0]), "+f"(d[1]), "+f"(d[2]), "+f"(d[3])
        : "r"(a[0]), "r"(a[1]), "r"(a[2]), "r"(a[3]), "r"(b[0]), "r"(b[1]));
}

// ---------------- init: Zc = Kopen @ Z ; Zold = Zc ----------------
__global__ void __launch_bounds__(256) k_init(const float* __restrict__ Z,
                                              const float* __restrict__ Kopen) {
    int c = blockIdx.x;
    __shared__ float kr[NSTART];
    if (threadIdx.x < NSTART) kr[threadIdx.x] = Kopen[c * NSTART + threadIdx.x];
    __syncthreads();
    for (int n = threadIdx.x; n < NN; n += 256) {
        float s = 0.f;
#pragma unroll
        for (int k = 0; k < NSTART; k++) s += kr[k] * Z[k * NN + n];
        g_Zc[c * NN + n] = s;
        g_Zold[c * NN + n] = s;
    }
}

// ---------------- Laplacian (fp32, every 10 layers) ----------------
__global__ void __launch_bounds__(256) k_sq() {
    int n = blockIdx.x * 256 + threadIdx.x;
    float s = 0.f;
#pragma unroll 4
    for (int c = 0; c < NOPEN; c++) {
        float v = g_Zc[c * NN + n];
        s += v * v;
    }
    g_sq[n] = s;
}

__global__ void __launch_bounds__(256) k_d2() {
    const int j0 = blockIdx.x * 64;
    const int i0 = blockIdx.y * 64;
    __shared__ float As[16 * 64];
    __shared__ float Bs[16 * 64];
    __shared__ float red[256];
    const int tid = threadIdx.x;
    const int tj = tid & 15, ti = tid >> 4;
    float acc[4][4] = {};
    for (int c = 0; c < 8; ++c) {
        int k0 = c * 16;
        for (int idx = tid; idx < 1024; idx += 256) {
            int k = idx >> 6, x = idx & 63;
            As[k * 64 + x] = g_Zc[(k0 + k) * NN + i0 + x];
            Bs[k * 64 + x] = g_Zc[(k0 + k) * NN + j0 + x];
        }
        __syncthreads();
#pragma unroll
        for (int kk = 0; kk < 16; ++kk) {
            float4 a = *(const float4*)&As[kk * 64 + ti * 4];
            float4 b = *(const float4*)&Bs[kk * 64 + tj * 4];
            acc[0][0] += a.x * b.x; acc[0][1] += a.x * b.y; acc[0][2] += a.x * b.z; acc[0][3] += a.x * b.w;
            acc[1][0] += a.y * b.x; acc[1][1] += a.y * b.y; acc[1][2] += a.y * b.z; acc[1][3] += a.y * b.w;
            acc[2][0] += a.z * b.x; acc[2][1] += a.z * b.y; acc[2][2] += a.z * b.z; acc[2][3] += a.z * b.w;
            acc[3][0] += a.w * b.x; acc[3][1] += a.w * b.y; acc[3][2] += a.w * b.z; acc[3][3] += a.w * b.w;
        }
        __syncthreads();
    }
    float lsum = 0.f;
#pragma unroll
    for (int r = 0; r < 4; ++r) {
        int i = i0 + ti * 4 + r;
        float sqi = g_sq[i];
        float4 o;
        float* po = (float*)&o;
#pragma unroll
        for (int cc = 0; cc < 4; ++cc) {
            int j = j0 + tj * 4 + cc;
            float d2 = fmaxf(sqi + g_sq[j] - 2.f * acc[r][cc], 0.f);
            po[cc] = d2;
            lsum += d2;
        }
        *(float4*)&g_W2[i * NN + j0 + tj * 4] = o;
    }
    red[tid] = lsum;
    __syncthreads();
    for (int o = 128; o > 0; o >>= 1) {
        if (tid < o) red[tid] += red[tid + o];
        __syncthreads();
    }
    if (tid == 0) g_part[blockIdx.y * 16 + blockIdx.x] = red[0];
}

__global__ void __launch_bounds__(256) k_sigma() {
    __shared__ float red[256];
    red[threadIdx.x] = g_part[threadIdx.x];
    __syncthreads();
    for (int o = 128; o > 0; o >>= 1) {
        if (threadIdx.x < o) red[threadIdx.x] += red[threadIdx.x + o];
        __syncthreads();
    }
    if (threadIdx.x == 0) g_sig = red[0];
}

__global__ void __launch_bounds__(256) k_wg() {
    int i = blockIdx.x;
    __shared__ float red[256];
    float sigma = g_sig * (1.f / 1048576.f) + 1e-12f;
    float inv = 1.f / sigma;
    float s = 0.f;
    for (int n = threadIdx.x; n < NN; n += 256) {
        float w = expf(-g_W2[i * NN + n] * inv);
        g_W2[i * NN + n] = w;
        s += w;
    }
    red[threadIdx.x] = s;
    __syncthreads();
    for (int o = 128; o > 0; o >>= 1) {
        if (threadIdx.x < o) red[threadIdx.x] += red[threadIdx.x + o];
        __syncthreads();
    }
    if (threadIdx.x == 0) g_deg[i] = red[0];
}

__global__ void __launch_bounds__(256) k_lap() {
    int i = blockIdx.x;
    float dhi = rsqrtf(g_deg[i]);
    for (int n = threadIdx.x; n < NN; n += 256) {
        float v = -dhi * rsqrtf(g_deg[n]) * g_W2[i * NN + n];
        if (n == i) v += 1.f;
        g_L[i * NN + n] = v;
    }
}

// L -> fragment-major tf32:
// g_Lfm[ ((k>>3)*128 + (n>>3))*64 + ((n&7)*4 + (k&3))*2 + ((k&7)>>2) ]
__global__ void __launch_bounds__(256) k_lapfm() {
    int idx = blockIdx.x * 256 + threadIdx.x;  // grid 4096
    int k = idx >> 10, n = idx & 1023;
    float v = g_L[idx];
    int off = ((k >> 3) * 128 + (n >> 3)) * 64 + ((n & 7) * 4 + (k & 3)) * 2 + ((k & 7) >> 2);
    g_Lfm[off] = f2t(v);
}

// ---------------- forward conv (implicit GEMM, tf32 mma) ----------------
// H_b[co, n] = sum_{ci,j} W[co,ci,j] * (Zc[ci, n+j-4] + bias[ci])
__global__ void __launch_bounds__(256) k_conv_mma(const float* __restrict__ W,
                                                  const float* __restrict__ Bias, int layer) {
    const int n0 = blockIdx.x * 128;
    const int m0 = blockIdx.y * 32;  // co tile
    const int b = blockIdx.z;
    const float* Wb = W + (size_t)(layer * 2 + b) * NHID * (NOPEN * 9);
    const float* Bb = Bias + (layer * 2 + b) * NOPEN;
    __shared__ __align__(16) uint32_t Xs[16 * 136];
    __shared__ __align__(16) uint32_t Asm[36 * 128];
    const int tid = threadIdx.x, lane = tid & 31, wrp = tid >> 5;
    const int wn0 = wrp * 16;
    float acc[2][2][4] = {};
    for (int cc = 0; cc < 8; ++cc) {
        int ci0 = cc * 16;
        {
            int ci = tid >> 4;
            float bias = Bb[ci0 + ci];
            const float* src = &g_Zc[(ci0 + ci) * NN];
            for (int t = tid & 15; t < 136; t += 16) {
                int m = n0 - 4 + t;
                float v = ((unsigned)m < (unsigned)NN) ? (src[m] + bias) : 0.f;
                Xs[ci * 136 + t] = f2t(v);
            }
        }
        for (int idx = tid; idx < 4608; idx += 256) {
            int co_l = idx / 144;
            int r = idx - co_l * 144;
            int ci_l = r / 9;
            int j = r - ci_l * 9;
            float v = Wb[(size_t)(m0 + co_l) * (NOPEN * 9) + (ci0 + ci_l) * 9 + j];
            int mf = co_l >> 4, row = co_l & 15;
            int cs = ci_l >> 3, col = ci_l & 7;
            int frag = (j * 2 + cs) * 2 + mf;
            int ln = (row & 7) * 4 + (col & 3);
            int e = (row >> 3) + ((col >> 2) << 1);
            Asm[frag * 128 + ln * 4 + e] = f2t(v);
        }
        __syncthreads();
#pragma unroll
        for (int j = 0; j < 9; ++j) {
#pragma unroll
            for (int cs = 0; cs < 2; ++cs) {
                int fb = ((j * 2 + cs) * 2) * 128 + lane * 4;
                uint32_t a0[4], a1[4];
                *(uint4*)a0 = *(const uint4*)&Asm[fb];
                *(uint4*)a1 = *(const uint4*)&Asm[fb + 128];
                int trow = cs * 8 + (lane & 3);
                int tb = wn0 + (lane >> 2) + j;
#pragma unroll
                for (int nf = 0; nf < 2; ++nf) {
                    uint32_t bb[2];
                    bb[0] = Xs[trow * 136 + tb + nf * 8];
                    bb[1] = Xs[(trow + 4) * 136 + tb + nf * 8];
                    mma8(acc[0][nf], a0, bb);
                    mma8(acc[1][nf], a1, bb);
                }
            }
        }
        __syncthreads();
    }
    float* H = b ? g_H1 : g_H0;
#pragma unroll
    for (int mf = 0; mf < 2; ++mf)
#pragma unroll
        for (int nf = 0; nf < 2; ++nf) {
            int m = m0 + mf * 16 + (lane >> 2);
            int n = n0 + wn0 + nf * 8 + (lane & 3) * 2;
            *(float2*)&H[m * NN + n] = make_float2(acc[mf][nf][0], acc[mf][nf][1]);
            *(float2*)&H[(m + 8) * NN + n] = make_float2(acc[mf][nf][2], acc[mf][nf][3]);
        }
}

// ---------------- GEMM: P[kh] = H1[:, kh*512:+512] @ L[kh*512:+512, :] ----------------
__global__ void __launch_bounds__(256) k_gemmHL_mma() {
    const int n0 = blockIdx.x * 128;
    const int m0 = blockIdx.y * 32;
    const int kh = blockIdx.z;
    __shared__ __align__(16) uint32_t Asmm[8 * 128];
    __shared__ __align__(16) uint32_t Bs[4 * 1024];
    const int tid = threadIdx.x, lane = tid & 31, wrp = tid >> 5;
    const int ngf0 = n0 >> 3;
    float acc[2][2][4] = {};
    for (int cc = 0; cc < 16; ++cc) {
        int k0 = kh * 512 + cc * 32;
        for (int idx = tid; idx < 1024; idx += 256) {
            int m = idx >> 5, k = idx & 31;
            float v = g_H1[(m0 + m) * NN + k0 + k];
            int ks = k >> 3, kl = k & 7;
            int mf = m >> 4, row = m & 15;
            int ln = (row & 7) * 4 + (kl & 3);
            int e = (row >> 3) + ((kl >> 2) << 1);
            Asmm[((ks * 2 + mf) * 32 + ln) * 4 + e] = f2t(v);
        }
        {
            const uint32_t* src = &g_Lfm[((k0 >> 3) * 128 + ngf0) * 64];
            for (int idx = tid; idx < 1024; idx += 256) {
                int ks = idx >> 8;
                int r = idx & 255;
                *(uint4*)&Bs[ks * 1024 + r * 4] = *(const uint4*)&src[ks * 8192 + r * 4];
            }
        }
        __syncthreads();
#pragma unroll
        for (int ks = 0; ks < 4; ++ks) {
            uint32_t a0[4], a1[4];
            *(uint4*)a0 = *(const uint4*)&Asmm[((ks * 2 + 0) * 32 + lane) * 4];
            *(uint4*)a1 = *(const uint4*)&Asmm[((ks * 2 + 1) * 32 + lane) * 4];
#pragma unroll
            for (int nf = 0; nf < 2; ++nf) {
                uint32_t bb[2];
                *(uint2*)bb = *(const uint2*)&Bs[((ks * 16 + wrp * 2 + nf) * 32 + lane) * 2];
                mma8(acc[0][nf], a0, bb);
                mma8(acc[1][nf], a1, bb);
            }
        }
        __syncthreads();
    }
    float* P = kh ? g_P1 : g_P0;
#pragma unroll
    for (int mf = 0; mf < 2; ++mf)
#pragma unroll
        for (int nf = 0; nf < 2; ++nf) {
            int m = m0 + mf * 16 + (lane >> 2);
            int n = n0 + wrp * 16 + nf * 8 + (lane & 3) * 2;
            *(float2*)&P[m * NN + n] = make_float2(acc[mf][nf][0], acc[mf][nf][1]);
            *(float2*)&P[(m + 8) * NN + n] = make_float2(acc[mf][nf][2], acc[mf][nf][3]);
        }
}

// ---------------- instance-norm stats ----------------
__global__ void __launch_bounds__(256) k_stats() {
    int ch = blockIdx.x;
    int b = ch >> 8, c = ch & 255;
    __shared__ float rs[256], rs2[256];
    float s = 0.f, s2 = 0.f;
    if (b == 0) {
        const float* p = &g_H0[c * NN];
        for (int n = threadIdx.x; n < NN; n += 256) {
            float v = p[n];
            s += v; s2 += v * v;
        }
    } else {
        const float* p0 = &g_P0[c * NN];
        const float* p1 = &g_P1[c * NN];
        for (int n = threadIdx.x; n < NN; n += 256) {
            float v = p0[n] + p1[n];
            s += v; s2 += v * v;
        }
    }
    rs[threadIdx.x] = s; rs2[threadIdx.x] = s2;
    __syncthreads();
    for (int o = 128; o > 0; o >>= 1) {
        if (threadIdx.x < o) { rs[threadIdx.x] += rs[threadIdx.x + o]; rs2[threadIdx.x] += rs2[threadIdx.x + o]; }
        __syncthreads();
    }
    if (threadIdx.x == 0) {
        float mean = rs[0] * (1.f / NN);
        float var = rs2[0] * (1.f / NN) - mean * mean;
        g_mean[ch] = mean;
        g_rstd[ch] = rsqrtf(var + 1e-5f);
    }
}

// ---------------- transposed conv (implicit GEMM, fused norm+relu) ----------------
// T[z][ci, n] = sum_{co in half, j} W[co,ci,j] * Y_b[co, n+4-j]
__global__ void __launch_bounds__(256) k_convT_mma(const float* __restrict__ W, int layer) {
    const int n0 = blockIdx.x * 128;
    const int m0 = blockIdx.y * 32;  // ci tile
    const int z = blockIdx.z;
    const int b = z >> 1, cos = z & 1;
    const float* Wb = W + (size_t)(layer * 2 + b) * NHID * (NOPEN * 9);
    __shared__ __align__(16) uint32_t Ys[16 * 136];
    __shared__ __align__(16) uint32_t Asm[36 * 128];
    const int tid = threadIdx.x, lane = tid & 31, wrp = tid >> 5;
    const int wn0 = wrp * 16;
    float acc[2][2][4] = {};
    for (int cc = 0; cc < 8; ++cc) {
        int co0 = cos * 128 + cc * 16;
        {
            int colh = tid >> 4;
            int co = co0 + colh;
            float mu = g_mean[b * 256 + co], rsd = g_rstd[b * 256 + co];
            for (int t = tid & 15; t < 136; t += 16) {
                int m = n0 - 4 + t;
                float v = 0.f;
                if ((unsigned)m < (unsigned)NN) {
                    float sv = b ? (g_P0[co * NN + m] + g_P1[co * NN + m]) : g_H0[co * NN + m];
                    v = fmaxf((sv - mu) * rsd, 0.f);
                }
                Ys[colh * 136 + t] = f2t(v);
            }
        }
        for (int idx = tid; idx < 4608; idx += 256) {
            int co_l = idx / 288;
            int r = idx - co_l * 288;
            int ci_l = r / 9;
            int j = r - ci_l * 9;
            float v = Wb[(size_t)(co0 + co_l) * (NOPEN * 9) + (m0 + ci_l) * 9 + j];
            int mf = ci_l >> 4, row = ci_l & 15;
            int cs = co_l >> 3, col = co_l & 7;
            int frag = (j * 2 + cs) * 2 + mf;
            int ln = (row & 7) * 4 + (col & 3);
            int e = (row >> 3) + ((col >> 2) << 1);
            Asm[frag * 128 + ln * 4 + e] = f2t(v);
        }
        __syncthreads();
#pragma unroll
        for (int j = 0; j < 9; ++j) {
#pragma unroll
            for (int cs = 0; cs < 2; ++cs) {
                int fb = ((j * 2 + cs) * 2) * 128 + lane * 4;
                uint32_t a0[4], a1[4];
                *(uint4*)a0 = *(const uint4*)&Asm[fb];
                *(uint4*)a1 = *(const uint4*)&Asm[fb + 128];
                int trow = cs * 8 + (lane & 3);
                int tb = wn0 + (lane >> 2) + (8 - j);
#pragma unroll
                for (int nf = 0; nf < 2; ++nf) {
                    uint32_t bb[2];
                    bb[0] = Ys[trow * 136 + tb + nf * 8];
                    bb[1] = Ys[(trow + 4) * 136 + tb + nf * 8];
                    mma8(acc[0][nf], a0, bb);
                    mma8(acc[1][nf], a1, bb);
                }
            }
        }
        __syncthreads();
    }
    float* T = g_T[z];
#pragma unroll
    for (int mf = 0; mf < 2; ++mf)
#pragma unroll
        for (int nf = 0; nf < 2; ++nf) {
            int m = m0 + mf * 16 + (lane >> 2);
            int n = n0 + wn0 + nf * 8 + (lane & 3) * 2;
            *(float2*)&T[m * NN + n] = make_float2(acc[mf][nf][0], acc[mf][nf][1]);
            *(float2*)&T[(m + 8) * NN + n] = make_float2(acc[mf][nf][2], acc[mf][nf][3]);
        }
}

// ---------------- GEMM: Q[kq] = (T2+T3)[:, kq*256:+256] @ L[kq*256:+256, :] ----------------
__global__ void __launch_bounds__(256) k_gemmQ_mma() {
    const int n0 = blockIdx.x * 128;
    const int m0 = blockIdx.y * 32;
    const int kq = blockIdx.z;
    __shared__ __align__(16) uint32_t Asmm[8 * 128];
    __shared__ __align__(16) uint32_t Bs[4 * 1024];
    const int tid = threadIdx.x, lane = tid & 31, wrp = tid >> 5;
    const int ngf0 = n0 >> 3;
    float acc[2][2][4] = {};
    for (int cc = 0; cc < 8; ++cc) {
        int k0 = kq * 256 + cc * 32;
        for (int idx = tid; idx < 1024; idx += 256) {
            int m = idx >> 5, k = idx & 31;
            int off = (m0 + m) * NN + k0 + k;
            float v = g_T[2][off] + g_T[3][off];
            int ks = k >> 3, kl = k & 7;
            int mf = m >> 4, row = m & 15;
            int ln = (row & 7) * 4 + (kl & 3);
            int e = (row >> 3) + ((kl >> 2) << 1);
            Asmm[((ks * 2 + mf) * 32 + ln) * 4 + e] = f2t(v);
        }
        {
            const uint32_t* src = &g_Lfm[((k0 >> 3) * 128 + ngf0) * 64];
            for (int idx = tid; idx < 1024; idx += 256) {
                int ks = idx >> 8;
                int r = idx & 255;
                *(uint4*)&Bs[ks * 1024 + r * 4] = *(const uint4*)&src[ks * 8192 + r * 4];
            }
        }
        __syncthreads();
#pragma unroll
        for (int ks = 0; ks < 4; ++ks) {
            uint32_t a0[4], a1[4];
            *(uint4*)a0 = *(const uint4*)&Asmm[((ks * 2 + 0) * 32 + lane) * 4];
            *(uint4*)a1 = *(const uint4*)&Asmm[((ks * 2 + 1) * 32 + lane) * 4];
#pragma unroll
            for (int nf = 0; nf < 2; ++nf) {
                uint32_t bb[2];
                *(uint2*)bb = *(const uint2*)&Bs[((ks * 16 + wrp * 2 + nf) * 32 + lane) * 2];
                mma8(acc[0][nf], a0, bb);
                mma8(acc[1][nf], a1, bb);
            }
        }
        __syncthreads();
    }
    float* Q = g_Q[kq];
#pragma unroll
    for (int mf = 0; mf < 2; ++mf)
#pragma unroll
        for (int nf = 0; nf < 2; ++nf) {
            int m = m0 + mf * 16 + (lane >> 2);
            int n = n0 + wrp * 16 + nf * 8 + (lane & 3) * 2;
            *(float2*)&Q[m * NN + n] = make_float2(acc[mf][nf][0], acc[mf][nf][1]);
            *(float2*)&Q[(m + 8) * NN + n] = make_float2(acc[mf][nf][2], acc[mf][nf][3]);
        }
}

// ---------------- leapfrog update ----------------
__global__ void __launch_bounds__(256) k_update() {
    int base = (blockIdx.x * 256 + threadIdx.x) * 4;
    float4 q0 = *(const float4*)&g_Q[0][base];
    float4 q1 = *(const float4*)&g_Q[1][base];
    float4 q2 = *(const float4*)&g_Q[2][base];
    float4 q3 = *(const float4*)&g_Q[3][base];
    float4 t0 = *(const float4*)&g_T[0][base];
    float4 t1 = *(const float4*)&g_T[1][base];
    float4 zc = *(const float4*)&g_Zc[base];
    float4 zo = *(const float4*)&g_Zold[base];
    float4 zn;
    zn.x = 2.f * zc.x - zo.x - 0.01f * (t0.x + t1.x + q0.x + q1.x + q2.x + q3.x);
    zn.y = 2.f * zc.y - zo.y - 0.01f * (t0.y + t1.y + q0.y + q1.y + q2.y + q3.y);
    zn.z = 2.f * zc.z - zo.z - 0.01f * (t0.z + t1.z + q0.z + q1.z + q2.z + q3.z);
    zn.w = 2.f * zc.w - zo.w - 0.01f * (t0.w + t1.w + q0.w + q1.w + q2.w + q3.w);
    *(float4*)&g_Zold[base] = zc;
    *(float4*)&g_Zc[base] = zn;
}

// ---------------- output ----------------
__global__ void __launch_bounds__(256) k_out(const float* __restrict__ Kclose,
                                             float* __restrict__ out) {
    int r = blockIdx.x % 3, sel = blockIdx.x / 3;
    const float* src = sel ? g_Zold : g_Zc;
    __shared__ float kc[NOPEN];
    if (threadIdx.x < NOPEN) kc[threadIdx.x] = Kclose[r * NOPEN + threadIdx.x];
    __syncthreads();
    for (int n = threadIdx.x; n < NN; n += 256) {
        float s = 0.f;
#pragma unroll 8
        for (int k = 0; k < NOPEN; k++) s += kc[k] * src[k * NN + n];
        out[sel * (NCLOSE * NN) + r * NN + n] = s;
    }
}

// ---------------- host ----------------
extern "C" void kernel_launch(void* const* d_in, const int* in_sizes, int n_in,
                              void* d_out, int out_size) {
    const float* Z      = (const float*)d_in[0];
    const float* Kopen  = (const float*)d_in[1];
    const float* Kclose = (const float*)d_in[2];
    const float* W      = (const float*)d_in[3];
    const float* Bias   = (const float*)d_in[4];
    float* out = (float*)d_out;

    k_init<<<128, 256>>>(Z, Kopen);
    for (int i = 0; i < NLAYERS; i++) {
        if (i % 10 == 0) {
            k_sq<<<4, 256>>>();
            k_d2<<<dim3(16, 16), 256>>>();
            k_sigma<<<1, 256>>>();
            k_wg<<<1024, 256>>>();
            k_lap<<<1024, 256>>>();
            k_lapfm<<<4096, 256>>>();
        }
        k_conv_mma<<<dim3(8, 8, 2), 256>>>(W, Bias, i);
        k_gemmHL_mma<<<dim3(8, 8, 2), 256>>>();
        k_stats<<<512, 256>>>();
        k_convT_mma<<<dim3(8, 4, 4), 256>>>(W, i);
        k_gemmQ_mma<<<dim3(8, 4, 4), 256>>>();
        k_update<<<128, 256>>>();
    }
    k_out<<<6, 256>>>(Kclose, out);
}

// round 4
// speedup vs baseline: 1.3480x; 1.1558x over previous
#include <cuda_runtime.h>
#include <cstdint>

#define NSTART 40
#define NOPEN 128
#define NHID 256
#define NCLOSE 3
#define NLAYERS 40
#define NN 1024

// ---------------- device scratch (static, allocation-free) ----------------
__device__ float g_Zc[NOPEN * NN];
__device__ float g_Zold[NOPEN * NN];
__device__ float g_L[NN * NN];
__device__ uint32_t g_Lfm[NN * NN];  // L in fragment-major tf32
__device__ float g_W2[NN * NN];
__device__ float g_deg[NN];
__device__ float g_sq[NN];
__device__ float g_part[256];
__device__ float g_sig;
__device__ float g_H0[NHID * NN];
__device__ float g_H1[NHID * NN];
__device__ float g_P0[NHID * NN];
__device__ float g_P1[NHID * NN];
__device__ float g_mean[2 * NHID];
__device__ float g_rstd[2 * NHID];
__device__ float g_T[4][NOPEN * NN];
__device__ float g_Q[4][NOPEN * NN];
// fragment-major tf32 weights, all layers:
// g_Wc: [(layer*2+b)][m-tile(8)][cc(8)][frag(36)][pos(128)]
// g_Wt: [(layer*2+b)][m-tile(4)][chunk(16)][frag(36)][pos(128)]
__device__ uint32_t g_Wc[40 * 2 * 8 * 8 * 36 * 128];
__device__ uint32_t g_Wt[40 * 2 * 4 * 16 * 36 * 128];

// ---------------- mma helpers ----------------
__device__ __forceinline__ uint32_t f2t(float x) {
    uint32_t r;
    asm("cvt.rna.tf32.f32 %0, %1;" : "=r"(r) : "f"(x));
    return r;
}
__device__ __forceinline__ void mma8(float* d, const uint32_t* a, const uint32_t* b) {
    asm volatile(
        "mma.sync.aligned.m16n8k8.row.col.f32.tf32.tf32.f32 "
        "{%0,%1,%2,%3}, {%4,%5,%6,%7}, {%8,%9}, {%0,%1,%2,%3};"
        : "+f"(d[0]), "+f"(d[1]), "+f"(d[2]), "+f"(d[3])
        : "r"(a[0]), "r"(a[1]), "r"(a[2]), "r"(a[3]), "r"(b[0]), "r"(b[1]));
}

// ---------------- weight preformat (once per replay) ----------------
__global__ void __launch_bounds__(256) k_wfmt_conv(const float* __restrict__ W) {
    int bid = blockIdx.x;                 // ((lb)*8 + mt)*8 + cc
    int cc = bid & 7, mt = (bid >> 3) & 7, lb = bid >> 6;
    __shared__ float Ws[4608];            // [co_l(32)][ci_l(16)][j(9)]
    const float* src = W + ((size_t)lb * 256 + mt * 32) * 1152 + cc * 144;
    for (int idx = threadIdx.x; idx < 4608; idx += 256) {
        int co_l = idx / 144, r = idx - co_l * 144;
        Ws[idx] = src[(size_t)co_l * 1152 + r];
    }
    __syncthreads();
    uint32_t* dst = g_Wc + (size_t)bid * 4608;
    for (int o = threadIdx.x; o < 4608; o += 256) {
        int frag = o >> 7, pos = o & 127;
        int j = frag >> 2, cs = (frag >> 1) & 1, mf = frag & 1;
        int ln = pos >> 2, e = pos & 3;
        int row = (ln >> 2) | ((e & 1) << 3);
        int col = (ln & 3) | ((e >> 1) << 2);
        int co_l = mf * 16 + row, ci_l = cs * 8 + col;
        dst[o] = f2t(Ws[co_l * 144 + ci_l * 9 + j]);
    }
}

__global__ void __launch_bounds__(256) k_wfmt_convT(const float* __restrict__ W) {
    int bid = blockIdx.x;                 // ((lb)*4 + mt)*16 + ch
    int ch = bid & 15, mt = (bid >> 4) & 3, lb = bid >> 6;
    __shared__ float Ws[4608];            // [co_l(16)][ci_l(32)][j(9)]
    const float* src = W + ((size_t)lb * 256 + ch * 16) * 1152 + mt * 288;
    for (int idx = threadIdx.x; idx < 4608; idx += 256) {
        int co_l = idx / 288, r = idx - co_l * 288;
        Ws[idx] = src[(size_t)co_l * 1152 + r];
    }
    __syncthreads();
    uint32_t* dst = g_Wt + (size_t)bid * 4608;
    for (int o = threadIdx.x; o < 4608; o += 256) {
        int frag = o >> 7, pos = o & 127;
        int j = frag >> 2, cs = (frag >> 1) & 1, mf = frag & 1;
        int ln = pos >> 2, e = pos & 3;
        int row = (ln >> 2) | ((e & 1) << 3);
        int col = (ln & 3) | ((e >> 1) << 2);
        int ci_l = mf * 16 + row, co_l = cs * 8 + col;
        dst[o] = f2t(Ws[co_l * 288 + ci_l * 9 + j]);
    }
}

// ---------------- init: Zc = Kopen @ Z ; Zold = Zc ----------------
__global__ void __launch_bounds__(256) k_init(const float* __restrict__ Z,
                                              const float* __restrict__ Kopen) {
    int c = blockIdx.x;
    __shared__ float kr[NSTART];
    if (threadIdx.x < NSTART) kr[threadIdx.x] = Kopen[c * NSTART + threadIdx.x];
    __syncthreads();
    for (int n = threadIdx.x; n < NN; n += 256) {
        float s = 0.f;
#pragma unroll
        for (int k = 0; k < NSTART; k++) s += kr[k] * Z[k * NN + n];
        g_Zc[c * NN + n] = s;
        g_Zold[c * NN + n] = s;
    }
}

// ---------------- Laplacian (fp32, every 10 layers) ----------------
__global__ void __launch_bounds__(256) k_sq() {
    int n = blockIdx.x * 256 + threadIdx.x;
    float s = 0.f;
#pragma unroll 4
    for (int c = 0; c < NOPEN; c++) {
        float v = g_Zc[c * NN + n];
        s += v * v;
    }
    g_sq[n] = s;
}

__global__ void __launch_bounds__(256) k_d2() {
    const int j0 = blockIdx.x * 64;
    const int i0 = blockIdx.y * 64;
    __shared__ float As[16 * 64];
    __shared__ float Bs[16 * 64];
    __shared__ float red[256];
    const int tid = threadIdx.x;
    const int tj = tid & 15, ti = tid >> 4;
    float acc[4][4] = {};
    for (int c = 0; c < 8; ++c) {
        int k0 = c * 16;
        for (int idx = tid; idx < 1024; idx += 256) {
            int k = idx >> 6, x = idx & 63;
            As[k * 64 + x] = g_Zc[(k0 + k) * NN + i0 + x];
            Bs[k * 64 + x] = g_Zc[(k0 + k) * NN + j0 + x];
        }
        __syncthreads();
#pragma unroll
        for (int kk = 0; kk < 16; ++kk) {
            float4 a = *(const float4*)&As[kk * 64 + ti * 4];
            float4 b = *(const float4*)&Bs[kk * 64 + tj * 4];
            acc[0][0] += a.x * b.x; acc[0][1] += a.x * b.y; acc[0][2] += a.x * b.z; acc[0][3] += a.x * b.w;
            acc[1][0] += a.y * b.x; acc[1][1] += a.y * b.y; acc[1][2] += a.y * b.z; acc[1][3] += a.y * b.w;
            acc[2][0] += a.z * b.x; acc[2][1] += a.z * b.y; acc[2][2] += a.z * b.z; acc[2][3] += a.z * b.w;
            acc[3][0] += a.w * b.x; acc[3][1] += a.w * b.y; acc[3][2] += a.w * b.z; acc[3][3] += a.w * b.w;
        }
        __syncthreads();
    }
    float lsum = 0.f;
#pragma unroll
    for (int r = 0; r < 4; ++r) {
        int i = i0 + ti * 4 + r;
        float sqi = g_sq[i];
        float4 o;
        float* po = (float*)&o;
#pragma unroll
        for (int cc = 0; cc < 4; ++cc) {
            int j = j0 + tj * 4 + cc;
            float d2 = fmaxf(sqi + g_sq[j] - 2.f * acc[r][cc], 0.f);
            po[cc] = d2;
            lsum += d2;
        }
        *(float4*)&g_W2[i * NN + j0 + tj * 4] = o;
    }
    red[tid] = lsum;
    __syncthreads();
    for (int o = 128; o > 0; o >>= 1) {
        if (tid < o) red[tid] += red[tid + o];
        __syncthreads();
    }
    if (tid == 0) g_part[blockIdx.y * 16 + blockIdx.x] = red[0];
}

__global__ void __launch_bounds__(256) k_sigma() {
    __shared__ float red[256];
    red[threadIdx.x] = g_part[threadIdx.x];
    __syncthreads();
    for (int o = 128; o > 0; o >>= 1) {
        if (threadIdx.x < o) red[threadIdx.x] += red[threadIdx.x + o];
        __syncthreads();
    }
    if (threadIdx.x == 0) g_sig = red[0];
}

__global__ void __launch_bounds__(256) k_wg() {
    int i = blockIdx.x;
    __shared__ float red[256];
    float sigma = g_sig * (1.f / 1048576.f) + 1e-12f;
    float inv = 1.f / sigma;
    float s = 0.f;
    for (int n = threadIdx.x; n < NN; n += 256) {
        float w = expf(-g_W2[i * NN + n] * inv);
        g_W2[i * NN + n] = w;
        s += w;
    }
    red[threadIdx.x] = s;
    __syncthreads();
    for (int o = 128; o > 0; o >>= 1) {
        if (threadIdx.x < o) red[threadIdx.x] += red[threadIdx.x + o];
        __syncthreads();
    }
    if (threadIdx.x == 0) g_deg[i] = red[0];
}

__global__ void __launch_bounds__(256) k_lap() {
    int i = blockIdx.x;
    float dhi = rsqrtf(g_deg[i]);
    for (int n = threadIdx.x; n < NN; n += 256) {
        float v = -dhi * rsqrtf(g_deg[n]) * g_W2[i * NN + n];
        if (n == i) v += 1.f;
        g_L[i * NN + n] = v;
    }
}

// L -> fragment-major tf32
__global__ void __launch_bounds__(256) k_lapfm() {
    int idx = blockIdx.x * 256 + threadIdx.x;  // grid 4096
    int k = idx >> 10, n = idx & 1023;
    float v = g_L[idx];
    int off = ((k >> 3) * 128 + (n >> 3)) * 64 + ((n & 7) * 4 + (k & 3)) * 2 + ((k & 7) >> 2);
    g_Lfm[off] = f2t(v);
}

// ---------------- forward conv (implicit GEMM, tf32 mma) ----------------
__global__ void __launch_bounds__(256) k_conv_mma(const float* __restrict__ Bias, int layer) {
    const int n0 = blockIdx.x * 128;
    const int m0 = blockIdx.y * 32;  // co tile
    const int b = blockIdx.z;
    const int lb = layer * 2 + b;
    const float* Bb = Bias + lb * NOPEN;
    __shared__ __align__(16) uint32_t Xs[16 * 136];
    __shared__ __align__(16) uint32_t Asm[36 * 128];
    const int tid = threadIdx.x, lane = tid & 31, wrp = tid >> 5;
    const int wn0 = wrp * 16;
    float acc[2][2][4] = {};
    for (int cc = 0; cc < 8; ++cc) {
        int ci0 = cc * 16;
        {
            int ci = tid >> 4;
            float bias = Bb[ci0 + ci];
            const float* src = &g_Zc[(ci0 + ci) * NN];
            for (int t = tid & 15; t < 136; t += 16) {
                int m = n0 - 4 + t;
                float v = ((unsigned)m < (unsigned)NN) ? (src[m] + bias) : 0.f;
                Xs[ci * 136 + t] = f2t(v);
            }
        }
        {
            const uint4* wsrc = (const uint4*)(g_Wc + ((size_t)((lb * 8 + blockIdx.y) * 8 + cc)) * 4608);
            for (int idx = tid; idx < 1152; idx += 256)
                ((uint4*)Asm)[idx] = wsrc[idx];
        }
        __syncthreads();
#pragma unroll
        for (int j = 0; j < 9; ++j) {
#pragma unroll
            for (int cs = 0; cs < 2; ++cs) {
                int fb = ((j * 2 + cs) * 2) * 128 + lane * 4;
                uint32_t a0[4], a1[4];
                *(uint4*)a0 = *(const uint4*)&Asm[fb];
                *(uint4*)a1 = *(const uint4*)&Asm[fb + 128];
                int trow = cs * 8 + (lane & 3);
                int tb = wn0 + (lane >> 2) + j;
#pragma unroll
                for (int nf = 0; nf < 2; ++nf) {
                    uint32_t bb[2];
                    bb[0] = Xs[trow * 136 + tb + nf * 8];
                    bb[1] = Xs[(trow + 4) * 136 + tb + nf * 8];
                    mma8(acc[0][nf], a0, bb);
                    mma8(acc[1][nf], a1, bb);
                }
            }
        }
        __syncthreads();
    }
    float* H = b ? g_H1 : g_H0;
#pragma unroll
    for (int mf = 0; mf < 2; ++mf)
#pragma unroll
        for (int nf = 0; nf < 2; ++nf) {
            int m = m0 + mf * 16 + (lane >> 2);
            int n = n0 + wn0 + nf * 8 + (lane & 3) * 2;
            *(float2*)&H[m * NN + n] = make_float2(acc[mf][nf][0], acc[mf][nf][1]);
            *(float2*)&H[(m + 8) * NN + n] = make_float2(acc[mf][nf][2], acc[mf][nf][3]);
        }
}

// ---------------- GEMM: P[kh] = H1[:, kh*512:+512] @ L[kh*512:+512, :] ----------------
__global__ void __launch_bounds__(256) k_gemmHL_mma() {
    const int n0 = blockIdx.x * 128;
    const int m0 = blockIdx.y * 32;
    const int kh = blockIdx.z;
    __shared__ __align__(16) uint32_t Asmm[8 * 128];
    __shared__ __align__(16) uint32_t Bs[4 * 1024];
    const int tid = threadIdx.x, lane = tid & 31, wrp = tid >> 5;
    const int ngf0 = n0 >> 3;
    float acc[2][2][4] = {};
    for (int cc = 0; cc < 16; ++cc) {
        int k0 = kh * 512 + cc * 32;
        for (int idx = tid; idx < 1024; idx += 256) {
            int m = idx >> 5, k = idx & 31;
            float v = g_H1[(m0 + m) * NN + k0 + k];
            int ks = k >> 3, kl = k & 7;
            int mf = m >> 4, row = m & 15;
            int ln = (row & 7) * 4 + (kl & 3);
            int e = (row >> 3) + ((kl >> 2) << 1);
            Asmm[((ks * 2 + mf) * 32 + ln) * 4 + e] = f2t(v);
        }
        {
            const uint32_t* src = &g_Lfm[((k0 >> 3) * 128 + ngf0) * 64];
            for (int idx = tid; idx < 1024; idx += 256) {
                int ks = idx >> 8;
                int r = idx & 255;
                *(uint4*)&Bs[ks * 1024 + r * 4] = *(const uint4*)&src[ks * 8192 + r * 4];
            }
        }
        __syncthreads();
#pragma unroll
        for (int ks = 0; ks < 4; ++ks) {
            uint32_t a0[4], a1[4];
            *(uint4*)a0 = *(const uint4*)&Asmm[((ks * 2 + 0) * 32 + lane) * 4];
            *(uint4*)a1 = *(const uint4*)&Asmm[((ks * 2 + 1) * 32 + lane) * 4];
#pragma unroll
            for (int nf = 0; nf < 2; ++nf) {
                uint32_t bb[2];
                *(uint2*)bb = *(const uint2*)&Bs[((ks * 16 + wrp * 2 + nf) * 32 + lane) * 2];
                mma8(acc[0][nf], a0, bb);
                mma8(acc[1][nf], a1, bb);
            }
        }
        __syncthreads();
    }
    float* P = kh ? g_P1 : g_P0;
#pragma unroll
    for (int mf = 0; mf < 2; ++mf)
#pragma unroll
        for (int nf = 0; nf < 2; ++nf) {
            int m = m0 + mf * 16 + (lane >> 2);
            int n = n0 + wrp * 16 + nf * 8 + (lane & 3) * 2;
            *(float2*)&P[m * NN + n] = make_float2(acc[mf][nf][0], acc[mf][nf][1]);
            *(float2*)&P[(m + 8) * NN + n] = make_float2(acc[mf][nf][2], acc[mf][nf][3]);
        }
}

// ---------------- instance-norm stats ----------------
__global__ void __launch_bounds__(256) k_stats() {
    int ch = blockIdx.x;
    int b = ch >> 8, c = ch & 255;
    __shared__ float rs[256], rs2[256];
    float s = 0.f, s2 = 0.f;
    if (b == 0) {
        const float* p = &g_H0[c * NN];
        for (int n = threadIdx.x; n < NN; n += 256) {
            float v = p[n];
            s += v; s2 += v * v;
        }
    } else {
        const float* p0 = &g_P0[c * NN];
        const float* p1 = &g_P1[c * NN];
        for (int n = threadIdx.x; n < NN; n += 256) {
            float v = p0[n] + p1[n];
            s += v; s2 += v * v;
        }
    }
    rs[threadIdx.x] = s; rs2[threadIdx.x] = s2;
    __syncthreads();
    for (int o = 128; o > 0; o >>= 1) {
        if (threadIdx.x < o) { rs[threadIdx.x] += rs[threadIdx.x + o]; rs2[threadIdx.x] += rs2[threadIdx.x + o]; }
        __syncthreads();
    }
    if (threadIdx.x == 0) {
        float mean = rs[0] * (1.f / NN);
        float var = rs2[0] * (1.f / NN) - mean * mean;
        g_mean[ch] = mean;
        g_rstd[ch] = rsqrtf(var + 1e-5f);
    }
}

// ---------------- transposed conv (implicit GEMM, fused norm+relu) ----------------
__global__ void __launch_bounds__(256) k_convT_mma(int layer) {
    const int n0 = blockIdx.x * 128;
    const int m0 = blockIdx.y * 32;  // ci tile
    const int z = blockIdx.z;
    const int b = z >> 1, cos = z & 1;
    const int lb = layer * 2 + b;
    __shared__ __align__(16) uint32_t Ys[16 * 136];
    __shared__ __align__(16) uint32_t Asm[36 * 128];
    const int tid = threadIdx.x, lane = tid & 31, wrp = tid >> 5;
    const int wn0 = wrp * 16;
    float acc[2][2][4] = {};
    for (int cc = 0; cc < 8; ++cc) {
        int co0 = cos * 128 + cc * 16;
        {
            int colh = tid >> 4;
            int co = co0 + colh;
            float mu = g_mean[b * 256 + co], rsd = g_rstd[b * 256 + co];
            for (int t = tid & 15; t < 136; t += 16) {
                int m = n0 - 4 + t;
                float v = 0.f;
                if ((unsigned)m < (unsigned)NN) {
                    float sv = b ? (g_P0[co * NN + m] + g_P1[co * NN + m]) : g_H0[co * NN + m];
                    v = fmaxf((sv - mu) * rsd, 0.f);
                }
                Ys[colh * 136 + t] = f2t(v);
            }
        }
        {
            const uint4* wsrc = (const uint4*)(g_Wt + ((size_t)((lb * 4 + blockIdx.y) * 16 + (cos * 8 + cc))) * 4608);
            for (int idx = tid; idx < 1152; idx += 256)
                ((uint4*)Asm)[idx] = wsrc[idx];
        }
        __syncthreads();
#pragma unroll
        for (int j = 0; j < 9; ++j) {
#pragma unroll
            for (int cs = 0; cs < 2; ++cs) {
                int fb = ((j * 2 + cs) * 2) * 128 + lane * 4;
                uint32_t a0[4], a1[4];
                *(uint4*)a0 = *(const uint4*)&Asm[fb];
                *(uint4*)a1 = *(const uint4*)&Asm[fb + 128];
                int trow = cs * 8 + (lane & 3);
                int tb = wn0 + (lane >> 2) + (8 - j);
#pragma unroll
                for (int nf = 0; nf < 2; ++nf) {
                    uint32_t bb[2];
                    bb[0] = Ys[trow * 136 + tb + nf * 8];
                    bb[1] = Ys[(trow + 4) * 136 + tb + nf * 8];
                    mma8(acc[0][nf], a0, bb);
                    mma8(acc[1][nf], a1, bb);
                }
            }
        }
        __syncthreads();
    }
    float* T = g_T[z];
#pragma unroll
    for (int mf = 0; mf < 2; ++mf)
#pragma unroll
        for (int nf = 0; nf < 2; ++nf) {
            int m = m0 + mf * 16 + (lane >> 2);
            int n = n0 + wn0 + nf * 8 + (lane & 3) * 2;
            *(float2*)&T[m * NN + n] = make_float2(acc[mf][nf][0], acc[mf][nf][1]);
            *(float2*)&T[(m + 8) * NN + n] = make_float2(acc[mf][nf][2], acc[mf][nf][3]);
        }
}

// ---------------- GEMM: Q[kq] = (T2+T3)[:, kq*256:+256] @ L[kq*256:+256, :] ----------------
__global__ void __launch_bounds__(256) k_gemmQ_mma() {
    const int n0 = blockIdx.x * 128;
    const int m0 = blockIdx.y * 32;
    const int kq = blockIdx.z;
    __shared__ __align__(16) uint32_t Asmm[8 * 128];
    __shared__ __align__(16) uint32_t Bs[4 * 1024];
    const int tid = threadIdx.x, lane = tid & 31, wrp = tid >> 5;
    const int ngf0 = n0 >> 3;
    float acc[2][2][4] = {};
    for (int cc = 0; cc < 8; ++cc) {
        int k0 = kq * 256 + cc * 32;
        for (int idx = tid; idx < 1024; idx += 256) {
            int m = idx >> 5, k = idx & 31;
            int off = (m0 + m) * NN + k0 + k;
            float v = g_T[2][off] + g_T[3][off];
            int ks = k >> 3, kl = k & 7;
            int mf = m >> 4, row = m & 15;
            int ln = (row & 7) * 4 + (kl & 3);
            int e = (row >> 3) + ((kl >> 2) << 1);
            Asmm[((ks * 2 + mf) * 32 + ln) * 4 + e] = f2t(v);
        }
        {
            const uint32_t* src = &g_Lfm[((k0 >> 3) * 128 + ngf0) * 64];
            for (int idx = tid; idx < 1024; idx += 256) {
                int ks = idx >> 8;
                int r = idx & 255;
                *(uint4*)&Bs[ks * 1024 + r * 4] = *(const uint4*)&src[ks * 8192 + r * 4];
            }
        }
        __syncthreads();
#pragma unroll
        for (int ks = 0; ks < 4; ++ks) {
            uint32_t a0[4], a1[4];
            *(uint4*)a0 = *(const uint4*)&Asmm[((ks * 2 + 0) * 32 + lane) * 4];
            *(uint4*)a1 = *(const uint4*)&Asmm[((ks * 2 + 1) * 32 + lane) * 4];
#pragma unroll
            for (int nf = 0; nf < 2; ++nf) {
                uint32_t bb[2];
                *(uint2*)bb = *(const uint2*)&Bs[((ks * 16 + wrp * 2 + nf) * 32 + lane) * 2];
                mma8(acc[0][nf], a0, bb);
                mma8(acc[1][nf], a1, bb);
            }
        }
        __syncthreads();
    }
    float* Q = g_Q[kq];
#pragma unroll
    for (int mf = 0; mf < 2; ++mf)
#pragma unroll
        for (int nf = 0; nf < 2; ++nf) {
            int m = m0 + mf * 16 + (lane >> 2);
            int n = n0 + wrp * 16 + nf * 8 + (lane & 3) * 2;
            *(float2*)&Q[m * NN + n] = make_float2(acc[mf][nf][0], acc[mf][nf][1]);
            *(float2*)&Q[(m + 8) * NN + n] = make_float2(acc[mf][nf][2], acc[mf][nf][3]);
        }
}

// ---------------- leapfrog update ----------------
__global__ void __launch_bounds__(256) k_update() {
    int base = (blockIdx.x * 256 + threadIdx.x) * 4;
    float4 q0 = *(const float4*)&g_Q[0][base];
    float4 q1 = *(const float4*)&g_Q[1][base];
    float4 q2 = *(const float4*)&g_Q[2][base];
    float4 q3 = *(const float4*)&g_Q[3][base];
    float4 t0 = *(const float4*)&g_T[0][base];
    float4 t1 = *(const float4*)&g_T[1][base];
    float4 zc = *(const float4*)&g_Zc[base];
    float4 zo = *(const float4*)&g_Zold[base];
    float4 zn;
    zn.x = 2.f * zc.x - zo.x - 0.01f * (t0.x + t1.x + q0.x + q1.x + q2.x + q3.x);
    zn.y = 2.f * zc.y - zo.y - 0.01f * (t0.y + t1.y + q0.y + q1.y + q2.y + q3.y);
    zn.z = 2.f * zc.z - zo.z - 0.01f * (t0.z + t1.z + q0.z + q1.z + q2.z + q3.z);
    zn.w = 2.f * zc.w - zo.w - 0.01f * (t0.w + t1.w + q0.w + q1.w + q2.w + q3.w);
    *(float4*)&g_Zold[base] = zc;
    *(float4*)&g_Zc[base] = zn;
}

// ---------------- output ----------------
__global__ void __launch_bounds__(256) k_out(const float* __restrict__ Kclose,
                                             float* __restrict__ out) {
    int r = blockIdx.x % 3, sel = blockIdx.x / 3;
    const float* src = sel ? g_Zold : g_Zc;
    __shared__ float kc[NOPEN];
    if (threadIdx.x < NOPEN) kc[threadIdx.x] = Kclose[r * NOPEN + threadIdx.x];
    __syncthreads();
    for (int n = threadIdx.x; n < NN; n += 256) {
        float s = 0.f;
#pragma unroll 8
        for (int k = 0; k < NOPEN; k++) s += kc[k] * src[k * NN + n];
        out[sel * (NCLOSE * NN) + r * NN + n] = s;
    }
}

// ---------------- host ----------------
extern "C" void kernel_launch(void* const* d_in, const int* in_sizes, int n_in,
                              void* d_out, int out_size) {
    const float* Z      = (const float*)d_in[0];
    const float* Kopen  = (const float*)d_in[1];
    const float* Kclose = (const float*)d_in[2];
    const float* W      = (const float*)d_in[3];
    const float* Bias   = (const float*)d_in[4];
    float* out = (float*)d_out;

    k_wfmt_conv<<<5120, 256>>>(W);
    k_wfmt_convT<<<5120, 256>>>(W);
    k_init<<<128, 256>>>(Z, Kopen);
    for (int i = 0; i < NLAYERS; i++) {
        if (i % 10 == 0) {
            k_sq<<<4, 256>>>();
            k_d2<<<dim3(16, 16), 256>>>();
            k_sigma<<<1, 256>>>();
            k_wg<<<1024, 256>>>();
            k_lap<<<1024, 256>>>();
            k_lapfm<<<4096, 256>>>();
        }
        k_conv_mma<<<dim3(8, 8, 2), 256>>>(Bias, i);
        k_gemmHL_mma<<<dim3(8, 8, 2), 256>>>();
        k_stats<<<512, 256>>>();
        k_convT_mma<<<dim3(8, 4, 4), 256>>>(i);
        k_gemmQ_mma<<<dim3(8, 4, 4), 256>>>();
        k_update<<<128, 256>>>();
    }
    k_out<<<6, 256>>>(Kclose, out);
}

// round 5
// speedup vs baseline: 1.9534x; 1.4491x over previous
#include <cuda_runtime.h>
#include <cstdint>

#define NSTART 40
#define NOPEN 128
#define NHID 256
#define NCLOSE 3
#define NLAYERS 40
#define NN 1024

// ---------------- device scratch (static, allocation-free) ----------------
__device__ float g_Zc[NOPEN * NN];
__device__ float g_Zold[NOPEN * NN];
__device__ float g_L[NN * NN];
__device__ uint32_t g_Lfm[NN * NN];  // L in fragment-major tf32
__device__ float g_W2[NN * NN];
__device__ float g_deg[NN];
__device__ float g_sq[NN];
__device__ float g_part[256];
__device__ float g_sig;
__device__ float g_H[4][NHID * NN];   // conv partials: [b*2 + ci_half]
__device__ float g_P[4][NHID * NN];   // H1@L partials: [k-quarter]
__device__ float g_mean[2 * NHID];
__device__ float g_rstd[2 * NHID];
__device__ float g_T[8][NOPEN * NN];  // convT partials: [b*4 + co_quarter]
__device__ float g_Q[8][NOPEN * NN];  // T1@L partials: [k-eighth]
// fragment-major tf32 weights, all layers:
// g_Wc: [(layer*2+b)][m-tile(8)][cc(8)][frag(36)][pos(128)]
// g_Wt: [(layer*2+b)][m-tile(4)][chunk(16)][frag(36)][pos(128)]
__device__ uint32_t g_Wc[40 * 2 * 8 * 8 * 36 * 128];
__device__ uint32_t g_Wt[40 * 2 * 4 * 16 * 36 * 128];

// ---------------- mma helpers ----------------
__device__ __forceinline__ uint32_t f2t(float x) {
    uint32_t r;
    asm("cvt.rna.tf32.f32 %0, %1;" : "=r"(r) : "f"(x));
    return r;
}
__device__ __forceinline__ void mma8(float* d, const uint32_t* a, const uint32_t* b) {
    asm volatile(
        "mma.sync.aligned.m16n8k8.row.col.f32.tf32.tf32.f32 "
        "{%0,%1,%2,%3}, {%4,%5,%6,%7}, {%8,%9}, {%0,%1,%2,%3};"
        : "+f"(d[0]), "+f"(d[1]), "+f"(d[2]), "+f"(d[3])
        : "r"(a[0]), "r"(a[1]), "r"(a[2]), "r"(a[3]), "r"(b[0]), "r"(b[1]));
}

// ---------------- weight preformat (once per replay) ----------------
__global__ void __launch_bounds__(256) k_wfmt_conv(const float* __restrict__ W) {
    int bid = blockIdx.x;                 // ((lb)*8 + mt)*8 + cc
    int cc = bid & 7, mt = (bid >> 3) & 7, lb = bid >> 6;
    __shared__ float Ws[4608];            // [co_l(32)][ci_l(16)][j(9)]
    const float* src = W + ((size_t)lb * 256 + mt * 32) * 1152 + cc * 144;
    for (int idx = threadIdx.x; idx < 4608; idx += 256) {
        int co_l = idx / 144, r = idx - co_l * 144;
        Ws[idx] = src[(size_t)co_l * 1152 + r];
    }
    __syncthreads();
    uint32_t* dst = g_Wc + (size_t)bid * 4608;
    for (int o = threadIdx.x; o < 4608; o += 256) {
        int frag = o >> 7, pos = o & 127;
        int j = frag >> 2, cs = (frag >> 1) & 1, mf = frag & 1;
        int ln = pos >> 2, e = pos & 3;
        int row = (ln >> 2) | ((e & 1) << 3);
        int col = (ln & 3) | ((e >> 1) << 2);
        int co_l = mf * 16 + row, ci_l = cs * 8 + col;
        dst[o] = f2t(Ws[co_l * 144 + ci_l * 9 + j]);
    }
}

__global__ void __launch_bounds__(256) k_wfmt_convT(const float* __restrict__ W) {
    int bid = blockIdx.x;                 // ((lb)*4 + mt)*16 + ch
    int ch = bid & 15, mt = (bid >> 4) & 3, lb = bid >> 6;
    __shared__ float Ws[4608];            // [co_l(16)][ci_l(32)][j(9)]
    const float* src = W + ((size_t)lb * 256 + ch * 16) * 1152 + mt * 288;
    for (int idx = threadIdx.x; idx < 4608; idx += 256) {
        int co_l = idx / 288, r = idx - co_l * 288;
        Ws[idx] = src[(size_t)co_l * 1152 + r];
    }
    __syncthreads();
    uint32_t* dst = g_Wt + (size_t)bid * 4608;
    for (int o = threadIdx.x; o < 4608; o += 256) {
        int frag = o >> 7, pos = o & 127;
        int j = frag >> 2, cs = (frag >> 1) & 1, mf = frag & 1;
        int ln = pos >> 2, e = pos & 3;
        int row = (ln >> 2) | ((e & 1) << 3);
        int col = (ln & 3) | ((e >> 1) << 2);
        int ci_l = mf * 16 + row, co_l = cs * 8 + col;
        dst[o] = f2t(Ws[co_l * 288 + ci_l * 9 + j]);
    }
}

// ---------------- init: Zc = Kopen @ Z ; Zold = Zc ----------------
__global__ void __launch_bounds__(256) k_init(const float* __restrict__ Z,
                                              const float* __restrict__ Kopen) {
    int c = blockIdx.x;
    __shared__ float kr[NSTART];
    if (threadIdx.x < NSTART) kr[threadIdx.x] = Kopen[c * NSTART + threadIdx.x];
    __syncthreads();
    for (int n = threadIdx.x; n < NN; n += 256) {
        float s = 0.f;
#pragma unroll
        for (int k = 0; k < NSTART; k++) s += kr[k] * Z[k * NN + n];
        g_Zc[c * NN + n] = s;
        g_Zold[c * NN + n] = s;
    }
}

// ---------------- Laplacian (fp32, every 10 layers) ----------------
__global__ void __launch_bounds__(256) k_sq() {
    // grid 16; block: 64 n x 4 c-groups
    int n = blockIdx.x * 64 + (threadIdx.x & 63);
    int cg = threadIdx.x >> 6;
    __shared__ float red[256];
    float s = 0.f;
#pragma unroll
    for (int c = cg * 32; c < cg * 32 + 32; c++) {
        float v = g_Zc[c * NN + n];
        s += v * v;
    }
    red[threadIdx.x] = s;
    __syncthreads();
    if (threadIdx.x < 64)
        g_sq[n] = red[threadIdx.x] + red[threadIdx.x + 64] + red[threadIdx.x + 128] + red[threadIdx.x + 192];
}

__global__ void __launch_bounds__(256) k_d2() {
    const int j0 = blockIdx.x * 64;
    const int i0 = blockIdx.y * 64;
    __shared__ float As[16 * 64];
    __shared__ float Bs[16 * 64];
    __shared__ float red[256];
    const int tid = threadIdx.x;
    const int tj = tid & 15, ti = tid >> 4;
    float acc[4][4] = {};
    for (int c = 0; c < 8; ++c) {
        int k0 = c * 16;
        for (int idx = tid; idx < 1024; idx += 256) {
            int k = idx >> 6, x = idx & 63;
            As[k * 64 + x] = g_Zc[(k0 + k) * NN + i0 + x];
            Bs[k * 64 + x] = g_Zc[(k0 + k) * NN + j0 + x];
        }
        __syncthreads();
#pragma unroll
        for (int kk = 0; kk < 16; ++kk) {
            float4 a = *(const float4*)&As[kk * 64 + ti * 4];
            float4 b = *(const float4*)&Bs[kk * 64 + tj * 4];
            acc[0][0] += a.x * b.x; acc[0][1] += a.x * b.y; acc[0][2] += a.x * b.z; acc[0][3] += a.x * b.w;
            acc[1][0] += a.y * b.x; acc[1][1] += a.y * b.y; acc[1][2] += a.y * b.z; acc[1][3] += a.y * b.w;
            acc[2][0] += a.z * b.x; acc[2][1] += a.z * b.y; acc[2][2] += a.z * b.z; acc[2][3] += a.z * b.w;
            acc[3][0] += a.w * b.x; acc[3][1] += a.w * b.y; acc[3][2] += a.w * b.z; acc[3][3] += a.w * b.w;
        }
        __syncthreads();
    }
    float lsum = 0.f;
#pragma unroll
    for (int r = 0; r < 4; ++r) {
        int i = i0 + ti * 4 + r;
        float sqi = g_sq[i];
        float4 o;
        float* po = (float*)&o;
#pragma unroll
        for (int cc = 0; cc < 4; ++cc) {
            int j = j0 + tj * 4 + cc;
            float d2 = fmaxf(sqi + g_sq[j] - 2.f * acc[r][cc], 0.f);
            po[cc] = d2;
            lsum += d2;
        }
        *(float4*)&g_W2[i * NN + j0 + tj * 4] = o;
    }
    red[tid] = lsum;
    __syncthreads();
    for (int o = 128; o > 0; o >>= 1) {
        if (tid < o) red[tid] += red[tid + o];
        __syncthreads();
    }
    if (tid == 0) g_part[blockIdx.y * 16 + blockIdx.x] = red[0];
}

__global__ void __launch_bounds__(256) k_sigma() {
    __shared__ float red[256];
    red[threadIdx.x] = g_part[threadIdx.x];
    __syncthreads();
    for (int o = 128; o > 0; o >>= 1) {
        if (threadIdx.x < o) red[threadIdx.x] += red[threadIdx.x + o];
        __syncthreads();
    }
    if (threadIdx.x == 0) g_sig = red[0];
}

__global__ void __launch_bounds__(256) k_wg() {
    int i = blockIdx.x;
    __shared__ float red[256];
    float sigma = g_sig * (1.f / 1048576.f) + 1e-12f;
    float inv = 1.f / sigma;
    float s = 0.f;
    for (int n = threadIdx.x; n < NN; n += 256) {
        float w = expf(-g_W2[i * NN + n] * inv);
        g_W2[i * NN + n] = w;
        s += w;
    }
    red[threadIdx.x] = s;
    __syncthreads();
    for (int o = 128; o > 0; o >>= 1) {
        if (threadIdx.x < o) red[threadIdx.x] += red[threadIdx.x + o];
        __syncthreads();
    }
    if (threadIdx.x == 0) g_deg[i] = red[0];
}

__global__ void __launch_bounds__(256) k_lap() {
    int i = blockIdx.x;
    float dhi = rsqrtf(g_deg[i]);
    for (int n = threadIdx.x; n < NN; n += 256) {
        float v = -dhi * rsqrtf(g_deg[n]) * g_W2[i * NN + n];
        if (n == i) v += 1.f;
        g_L[i * NN + n] = v;
    }
}

// L -> fragment-major tf32
__global__ void __launch_bounds__(256) k_lapfm() {
    int idx = blockIdx.x * 256 + threadIdx.x;  // grid 4096
    int k = idx >> 10, n = idx & 1023;
    float v = g_L[idx];
    int off = ((k >> 3) * 128 + (n >> 3)) * 64 + ((n & 7) * 4 + (k & 3)) * 2 + ((k & 7) >> 2);
    g_Lfm[off] = f2t(v);
}

// ---------------- forward conv (implicit GEMM, 32x256 tile, ci-half split) ----------------
__global__ void __launch_bounds__(256) k_conv_mma(const float* __restrict__ Bias, int layer) {
    const int n0 = blockIdx.x * 256;
    const int mt = blockIdx.y;            // co tile (0..7)
    const int m0 = mt * 32;
    const int b = blockIdx.z >> 1, ch = blockIdx.z & 1;
    const int lb = layer * 2 + b;
    const float* Bb = Bias + lb * NOPEN;
    __shared__ __align__(16) uint32_t Xs[16 * 264];
    __shared__ __align__(16) uint32_t Asm[36 * 128];
    const int tid = threadIdx.x, lane = tid & 31, wrp = tid >> 5;
    const int wn0 = wrp * 32;
    float acc[2][4][4] = {};
    for (int cc = 0; cc < 4; ++cc) {
        int ci0 = ch * 64 + cc * 16;
        {
            int ci = tid >> 4;
            float bias = Bb[ci0 + ci];
            const float* src = &g_Zc[(ci0 + ci) * NN];
            for (int t = tid & 15; t < 264; t += 16) {
                int m = n0 - 4 + t;
                float v = ((unsigned)m < (unsigned)NN) ? (src[m] + bias) : 0.f;
                Xs[ci * 264 + t] = f2t(v);
            }
        }
        {
            const uint4* wsrc = (const uint4*)(g_Wc + ((size_t)((lb * 8 + mt) * 8 + ch * 4 + cc)) * 4608);
            for (int idx = tid; idx < 1152; idx += 256)
                ((uint4*)Asm)[idx] = wsrc[idx];
        }
        __syncthreads();
#pragma unroll
        for (int j = 0; j < 9; ++j) {
#pragma unroll
            for (int cs = 0; cs < 2; ++cs) {
                int fb = ((j * 2 + cs) * 2) * 128 + lane * 4;
                uint32_t a0[4], a1[4];
                *(uint4*)a0 = *(const uint4*)&Asm[fb];
                *(uint4*)a1 = *(const uint4*)&Asm[fb + 128];
                int trow = cs * 8 + (lane & 3);
                int tb = wn0 + (lane >> 2) + j;
#pragma unroll
                for (int nf = 0; nf < 4; ++nf) {
                    uint32_t bb[2];
                    bb[0] = Xs[trow * 264 + tb + nf * 8];
                    bb[1] = Xs[(trow + 4) * 264 + tb + nf * 8];
                    mma8(acc[0][nf], a0, bb);
                    mma8(acc[1][nf], a1, bb);
                }
            }
        }
        __syncthreads();
    }
    float* H = g_H[b * 2 + ch];
#pragma unroll
    for (int mf = 0; mf < 2; ++mf)
#pragma unroll
        for (int nf = 0; nf < 4; ++nf) {
            int m = m0 + mf * 16 + (lane >> 2);
            int n = n0 + wn0 + nf * 8 + (lane & 3) * 2;
            *(float2*)&H[m * NN + n] = make_float2(acc[mf][nf][0], acc[mf][nf][1]);
            *(float2*)&H[(m + 8) * NN + n] = make_float2(acc[mf][nf][2], acc[mf][nf][3]);
        }
}

// ---------------- GEMM: P[kq] = H1[:, kq*256:+256] @ L[kq*256:+256, :] ----------------
__global__ void __launch_bounds__(256) k_gemmHL_mma() {
    const int n0 = blockIdx.x * 256;
    const int m0 = blockIdx.y * 32;
    const int kq = blockIdx.z;            // 0..3
    __shared__ __align__(16) uint32_t Asmm[8 * 128];
    __shared__ __align__(16) uint32_t Bs[8192];
    const int tid = threadIdx.x, lane = tid & 31, wrp = tid >> 5;
    const int ngf0 = n0 >> 3;             // 32 n-groups per block
    float acc[2][4][4] = {};
    for (int cc = 0; cc < 8; ++cc) {
        int k0 = kq * 256 + cc * 32;
        for (int idx = tid; idx < 1024; idx += 256) {
            int m = idx >> 5, k = idx & 31;
            int off = (m0 + m) * NN + k0 + k;
            float v = g_H[2][off] + g_H[3][off];
            int ks = k >> 3, kl = k & 7;
            int mf = m >> 4, row = m & 15;
            int ln = (row & 7) * 4 + (kl & 3);
            int e = (row >> 3) + ((kl >> 2) << 1);
            Asmm[((ks * 2 + mf) * 32 + ln) * 4 + e] = f2t(v);
        }
        for (int idx = tid; idx < 2048; idx += 256) {
            int ks = idx >> 9, r = idx & 511;
            ((uint4*)Bs)[idx] = *((const uint4*)(g_Lfm + ((size_t)((k0 >> 3) + ks) * 128 + ngf0) * 64) + r);
        }
        __syncthreads();
#pragma unroll
        for (int ks = 0; ks < 4; ++ks) {
            uint32_t a0[4], a1[4];
            *(uint4*)a0 = *(const uint4*)&Asmm[((ks * 2 + 0) * 32 + lane) * 4];
            *(uint4*)a1 = *(const uint4*)&Asmm[((ks * 2 + 1) * 32 + lane) * 4];
#pragma unroll
            for (int nf = 0; nf < 4; ++nf) {
                uint32_t bb[2];
                *(uint2*)bb = *(const uint2*)&Bs[((ks * 32 + wrp * 4 + nf) * 32 + lane) * 2];
                mma8(acc[0][nf], a0, bb);
                mma8(acc[1][nf], a1, bb);
            }
        }
        __syncthreads();
    }
    float* P = g_P[kq];
#pragma unroll
    for (int mf = 0; mf < 2; ++mf)
#pragma unroll
        for (int nf = 0; nf < 4; ++nf) {
            int m = m0 + mf * 16 + (lane >> 2);
            int n = n0 + wrp * 32 + nf * 8 + (lane & 3) * 2;
            *(float2*)&P[m * NN + n] = make_float2(acc[mf][nf][0], acc[mf][nf][1]);
            *(float2*)&P[(m + 8) * NN + n] = make_float2(acc[mf][nf][2], acc[mf][nf][3]);
        }
}

// ---------------- instance-norm stats ----------------
__global__ void __launch_bounds__(256) k_stats() {
    int ch = blockIdx.x;
    int b = ch >> 8, c = ch & 255;
    __shared__ float rs[256], rs2[256];
    float s = 0.f, s2 = 0.f;
    if (b == 0) {
        const float* p0 = &g_H[0][c * NN];
        const float* p1 = &g_H[1][c * NN];
        for (int n = threadIdx.x; n < NN; n += 256) {
            float v = p0[n] + p1[n];
            s += v; s2 += v * v;
        }
    } else {
        const float* p0 = &g_P[0][c * NN];
        const float* p1 = &g_P[1][c * NN];
        const float* p2 = &g_P[2][c * NN];
        const float* p3 = &g_P[3][c * NN];
        for (int n = threadIdx.x; n < NN; n += 256) {
            float v = p0[n] + p1[n] + p2[n] + p3[n];
            s += v; s2 += v * v;
        }
    }
    rs[threadIdx.x] = s; rs2[threadIdx.x] = s2;
    __syncthreads();
    for (int o = 128; o > 0; o >>= 1) {
        if (threadIdx.x < o) { rs[threadIdx.x] += rs[threadIdx.x + o]; rs2[threadIdx.x] += rs2[threadIdx.x + o]; }
        __syncthreads();
    }
    if (threadIdx.x == 0) {
        float mean = rs[0] * (1.f / NN);
        float var = rs2[0] * (1.f / NN) - mean * mean;
        g_mean[ch] = mean;
        g_rstd[ch] = rsqrtf(var + 1e-5f);
    }
}

// ---------------- transposed conv (32x256 tile, co-quarter split, fused norm+relu) --------
__global__ void __launch_bounds__(256) k_convT_mma(int layer) {
    const int n0 = blockIdx.x * 256;
    const int mt = blockIdx.y;            // ci tile (0..3)
    const int m0 = mt * 32;
    const int b = blockIdx.z >> 2, q = blockIdx.z & 3;
    const int lb = layer * 2 + b;
    __shared__ __align__(16) uint32_t Ys[16 * 264];
    __shared__ __align__(16) uint32_t Asm[36 * 128];
    const int tid = threadIdx.x, lane = tid & 31, wrp = tid >> 5;
    const int wn0 = wrp * 32;
    float acc[2][4][4] = {};
    for (int cc = 0; cc < 4; ++cc) {
        int chunk = q * 4 + cc;
        int co0 = chunk * 16;
        {
            int colh = tid >> 4;
            int co = co0 + colh;
            float mu = g_mean[b * 256 + co], rsd = g_rstd[b * 256 + co];
            for (int t = tid & 15; t < 264; t += 16) {
                int m = n0 - 4 + t;
                float v = 0.f;
                if ((unsigned)m < (unsigned)NN) {
                    int off = co * NN + m;
                    float sv = b ? (g_P[0][off] + g_P[1][off] + g_P[2][off] + g_P[3][off])
                                 : (g_H[0][off] + g_H[1][off]);
                    v = fmaxf((sv - mu) * rsd, 0.f);
                }
                Ys[colh * 264 + t] = f2t(v);
            }
        }
        {
            const uint4* wsrc = (const uint4*)(g_Wt + ((size_t)((lb * 4 + mt) * 16 + chunk)) * 4608);
            for (int idx = tid; idx < 1152; idx += 256)
                ((uint4*)Asm)[idx] = wsrc[idx];
        }
        __syncthreads();
#pragma unroll
        for (int j = 0; j < 9; ++j) {
#pragma unroll
            for (int cs = 0; cs < 2; ++cs) {
                int fb = ((j * 2 + cs) * 2) * 128 + lane * 4;
                uint32_t a0[4], a1[4];
                *(uint4*)a0 = *(const uint4*)&Asm[fb];
                *(uint4*)a1 = *(const uint4*)&Asm[fb + 128];
                int trow = cs * 8 + (lane & 3);
                int tb = wn0 + (lane >> 2) + (8 - j);
#pragma unroll
                for (int nf = 0; nf < 4; ++nf) {
                    uint32_t bb[2];
                    bb[0] = Ys[trow * 264 + tb + nf * 8];
                    bb[1] = Ys[(trow + 4) * 264 + tb + nf * 8];
                    mma8(acc[0][nf], a0, bb);
                    mma8(acc[1][nf], a1, bb);
                }
            }
        }
        __syncthreads();
    }
    float* T = g_T[b * 4 + q];
#pragma unroll
    for (int mf = 0; mf < 2; ++mf)
#pragma unroll
        for (int nf = 0; nf < 4; ++nf) {
            int m = m0 + mf * 16 + (lane >> 2);
            int n = n0 + wn0 + nf * 8 + (lane & 3) * 2;
            *(float2*)&T[m * NN + n] = make_float2(acc[mf][nf][0], acc[mf][nf][1]);
            *(float2*)&T[(m + 8) * NN + n] = make_float2(acc[mf][nf][2], acc[mf][nf][3]);
        }
}

// ---------------- GEMM: Q[kq] = T1[:, kq*128:+128] @ L[kq*128:+128, :] ----------------
__global__ void __launch_bounds__(256) k_gemmQ_mma() {
    const int n0 = blockIdx.x * 256;
    const int m0 = blockIdx.y * 32;
    const int kq = blockIdx.z;            // 0..7
    __shared__ __align__(16) uint32_t Asmm[8 * 128];
    __shared__ __align__(16) uint32_t Bs[8192];
    const int tid = threadIdx.x, lane = tid & 31, wrp = tid >> 5;
    const int ngf0 = n0 >> 3;
    float acc[2][4][4] = {};
    for (int cc = 0; cc < 4; ++cc) {
        int k0 = kq * 128 + cc * 32;
        for (int idx = tid; idx < 1024; idx += 256) {
            int m = idx >> 5, k = idx & 31;
            int off = (m0 + m) * NN + k0 + k;
            float v = g_T[4][off] + g_T[5][off] + g_T[6][off] + g_T[7][off];
            int ks = k >> 3, kl = k & 7;
            int mf = m >> 4, row = m & 15;
            int ln = (row & 7) * 4 + (kl & 3);
            int e = (row >> 3) + ((kl >> 2) << 1);
            Asmm[((ks * 2 + mf) * 32 + ln) * 4 + e] = f2t(v);
        }
        for (int idx = tid; idx < 2048; idx += 256) {
            int ks = idx >> 9, r = idx & 511;
            ((uint4*)Bs)[idx] = *((const uint4*)(g_Lfm + ((size_t)((k0 >> 3) + ks) * 128 + ngf0) * 64) + r);
        }
        __syncthreads();
#pragma unroll
        for (int ks = 0; ks < 4; ++ks) {
            uint32_t a0[4], a1[4];
            *(uint4*)a0 = *(const uint4*)&Asmm[((ks * 2 + 0) * 32 + lane) * 4];
            *(uint4*)a1 = *(const uint4*)&Asmm[((ks * 2 + 1) * 32 + lane) * 4];
#pragma unroll
            for (int nf = 0; nf < 4; ++nf) {
                uint32_t bb[2];
                *(uint2*)bb = *(const uint2*)&Bs[((ks * 32 + wrp * 4 + nf) * 32 + lane) * 2];
                mma8(acc[0][nf], a0, bb);
                mma8(acc[1][nf], a1, bb);
            }
        }
        __syncthreads();
    }
    float* Q = g_Q[kq];
#pragma unroll
    for (int mf = 0; mf < 2; ++mf)
#pragma unroll
        for (int nf = 0; nf < 4; ++nf) {
            int m = m0 + mf * 16 + (lane >> 2);
            int n = n0 + wrp * 32 + nf * 8 + (lane & 3) * 2;
            *(float2*)&Q[m * NN + n] = make_float2(acc[mf][nf][0], acc[mf][nf][1]);
            *(float2*)&Q[(m + 8) * NN + n] = make_float2(acc[mf][nf][2], acc[mf][nf][3]);
        }
}

// ---------------- leapfrog update ----------------
__global__ void __launch_bounds__(256) k_update() {
    int base = (blockIdx.x * 256 + threadIdx.x) * 4;
    float4 a0 = *(const float4*)&g_T[0][base];
    float4 a1 = *(const float4*)&g_T[1][base];
    float4 a2 = *(const float4*)&g_T[2][base];
    float4 a3 = *(const float4*)&g_T[3][base];
    float sx = a0.x + a1.x + a2.x + a3.x;
    float sy = a0.y + a1.y + a2.y + a3.y;
    float sz = a0.z + a1.z + a2.z + a3.z;
    float sw = a0.w + a1.w + a2.w + a3.w;
#pragma unroll
    for (int q = 0; q < 8; ++q) {
        float4 t = *(const float4*)&g_Q[q][base];
        sx += t.x; sy += t.y; sz += t.z; sw += t.w;
    }
    float4 zc = *(const float4*)&g_Zc[base];
    float4 zo = *(const float4*)&g_Zold[base];
    float4 zn;
    zn.x = 2.f * zc.x - zo.x - 0.01f * sx;
    zn.y = 2.f * zc.y - zo.y - 0.01f * sy;
    zn.z = 2.f * zc.z - zo.z - 0.01f * sz;
    zn.w = 2.f * zc.w - zo.w - 0.01f * sw;
    *(float4*)&g_Zold[base] = zc;
    *(float4*)&g_Zc[base] = zn;
}

// ---------------- output ----------------
__global__ void __launch_bounds__(256) k_out(const float* __restrict__ Kclose,
                                             float* __restrict__ out) {
    int r = blockIdx.x % 3, sel = blockIdx.x / 3;
    const float* src = sel ? g_Zold : g_Zc;
    __shared__ float kc[NOPEN];
    if (threadIdx.x < NOPEN) kc[threadIdx.x] = Kclose[r * NOPEN + threadIdx.x];
    __syncthreads();
    for (int n = threadIdx.x; n < NN; n += 256) {
        float s = 0.f;
#pragma unroll 8
        for (int k = 0; k < NOPEN; k++) s += kc[k] * src[k * NN + n];
        out[sel * (NCLOSE * NN) + r * NN + n] = s;
    }
}

// ---------------- host ----------------
extern "C" void kernel_launch(void* const* d_in, const int* in_sizes, int n_in,
                              void* d_out, int out_size) {
    const float* Z      = (const float*)d_in[0];
    const float* Kopen  = (const float*)d_in[1];
    const float* Kclose = (const float*)d_in[2];
    const float* W      = (const float*)d_in[3];
    const float* Bias   = (const float*)d_in[4];
    float* out = (float*)d_out;

    k_wfmt_conv<<<5120, 256>>>(W);
    k_wfmt_convT<<<5120, 256>>>(W);
    k_init<<<128, 256>>>(Z, Kopen);
    for (int i = 0; i < NLAYERS; i++) {
        if (i % 10 == 0) {
            k_sq<<<16, 256>>>();
            k_d2<<<dim3(16, 16), 256>>>();
            k_sigma<<<1, 256>>>();
            k_wg<<<1024, 256>>>();
            k_lap<<<1024, 256>>>();
            k_lapfm<<<4096, 256>>>();
        }
        k_conv_mma<<<dim3(4, 8, 4), 256>>>(Bias, i);
        k_gemmHL_mma<<<dim3(4, 8, 4), 256>>>();
        k_stats<<<512, 256>>>();
        k_convT_mma<<<dim3(4, 4, 8), 256>>>(i);
        k_gemmQ_mma<<<dim3(4, 4, 8), 256>>>();
        k_update<<<128, 256>>>();
    }
    k_out<<<6, 256>>>(Kclose, out);
}

// round 6
// speedup vs baseline: 4.4364x; 2.2711x over previous
#include <cuda_runtime.h>
#include <cstdint>

#define NSTART 40
#define NOPEN 128
#define NHID 256
#define NCLOSE 3
#define NLAYERS 40
#define NN 1024
#define XROW 1032   // 4 halo + 1024 + 4 halo

// ---------------- device scratch (static, allocation-free) ----------------
__device__ __align__(16) float g_Zc[NOPEN * NN];
__device__ __align__(16) float g_Zold[NOPEN * NN];
__device__ __align__(16) float g_L[NN * NN];
__device__ __align__(16) uint32_t g_Lfm[NN * NN];
__device__ __align__(16) float g_W2[NN * NN];
__device__ float g_deg[NN];
__device__ float g_sq[NN];
__device__ float g_part[256];
__device__ float g_sig;
__device__ __align__(16) float g_H[4][NHID * NN];   // conv partials [b*2+ci_half]
__device__ __align__(16) float g_P[4][NHID * NN];   // H1@L partials [k-quarter]
__device__ __align__(16) float g_T[8][NOPEN * NN];  // convT partials [b*4+co_quarter]
__device__ __align__(16) float g_Q[8][NOPEN * NN];  // T1@L partials [k-eighth]
__device__ __align__(16) float g_X[2][NOPEN * XROW];   // Zc+bias, halo'd (zeros at edges)
__device__ __align__(16) float g_Y[2][NHID * XROW];    // relu(norm(.)), halo'd
__device__ uint32_t g_Wc[40 * 2 * 8 * 8 * 36 * 128];
__device__ uint32_t g_Wt[40 * 2 * 4 * 16 * 36 * 128];

// ---------------- helpers ----------------
__device__ __forceinline__ uint32_t f2t(float x) {
    uint32_t r;
    asm("cvt.rna.tf32.f32 %0, %1;" : "=r"(r) : "f"(x));
    return r;
}
__device__ __forceinline__ void mma8(float* d, const uint32_t* a, const uint32_t* b) {
    asm volatile(
        "mma.sync.aligned.m16n8k8.row.col.f32.tf32.tf32.f32 "
        "{%0,%1,%2,%3}, {%4,%5,%6,%7}, {%8,%9}, {%0,%1,%2,%3};"
        : "+f"(d[0]), "+f"(d[1]), "+f"(d[2]), "+f"(d[3])
        : "r"(a[0]), "r"(a[1]), "r"(a[2]), "r"(a[3]), "r"(b[0]), "r"(b[1]));
}
__device__ __forceinline__ void cp16(uint32_t smem, const void* gmem) {
    asm volatile("cp.async.cg.shared.global [%0], [%1], 16;\n" :: "r"(smem), "l"(gmem));
}
__device__ __forceinline__ void cp_commit() { asm volatile("cp.async.commit_group;\n"); }
__device__ __forceinline__ void cp_wait1() { asm volatile("cp.async.wait_group 1;\n"); }
__device__ __forceinline__ void cp_wait0() { asm volatile("cp.async.wait_group 0;\n"); }

// ---------------- weight preformat ----------------
__global__ void __launch_bounds__(256) k_wfmt_conv(const float* __restrict__ W) {
    int bid = blockIdx.x;
    int cc = bid & 7, mt = (bid >> 3) & 7, lb = bid >> 6;
    __shared__ float Ws[4608];
    const float* src = W + ((size_t)lb * 256 + mt * 32) * 1152 + cc * 144;
    for (int idx = threadIdx.x; idx < 4608; idx += 256) {
        int co_l = idx / 144, r = idx - co_l * 144;
        Ws[idx] = src[(size_t)co_l * 1152 + r];
    }
    __syncthreads();
    uint32_t* dst = g_Wc + (size_t)bid * 4608;
    for (int o = threadIdx.x; o < 4608; o += 256) {
        int frag = o >> 7, pos = o & 127;
        int j = frag >> 2, cs = (frag >> 1) & 1, mf = frag & 1;
        int ln = pos >> 2, e = pos & 3;
        int row = (ln >> 2) | ((e & 1) << 3);
        int col = (ln & 3) | ((e >> 1) << 2);
        int co_l = mf * 16 + row, ci_l = cs * 8 + col;
        dst[o] = f2t(Ws[co_l * 144 + ci_l * 9 + j]);
    }
}

__global__ void __launch_bounds__(256) k_wfmt_convT(const float* __restrict__ W) {
    int bid = blockIdx.x;
    int ch = bid & 15, mt = (bid >> 4) & 3, lb = bid >> 6;
    __shared__ float Ws[4608];
    const float* src = W + ((size_t)lb * 256 + ch * 16) * 1152 + mt * 288;
    for (int idx = threadIdx.x; idx < 4608; idx += 256) {
        int co_l = idx / 288, r = idx - co_l * 288;
        Ws[idx] = src[(size_t)co_l * 1152 + r];
    }
    __syncthreads();
    uint32_t* dst = g_Wt + (size_t)bid * 4608;
    for (int o = threadIdx.x; o < 4608; o += 256) {
        int frag = o >> 7, pos = o & 127;
        int j = frag >> 2, cs = (frag >> 1) & 1, mf = frag & 1;
        int ln = pos >> 2, e = pos & 3;
        int row = (ln >> 2) | ((e & 1) << 3);
        int col = (ln & 3) | ((e >> 1) << 2);
        int ci_l = mf * 16 + row, co_l = cs * 8 + col;
        dst[o] = f2t(Ws[co_l * 288 + ci_l * 9 + j]);
    }
}

// ---------------- init: Zc = Kopen @ Z ; Zold = Zc ; X for layer 0 ----------------
__global__ void __launch_bounds__(256) k_init(const float* __restrict__ Z,
                                              const float* __restrict__ Kopen,
                                              const float* __restrict__ Bias) {
    int c = blockIdx.x;
    __shared__ float kr[NSTART];
    if (threadIdx.x < NSTART) kr[threadIdx.x] = Kopen[c * NSTART + threadIdx.x];
    __syncthreads();
    float b0 = Bias[c], b1 = Bias[NOPEN + c];
    for (int n = threadIdx.x; n < NN; n += 256) {
        float s = 0.f;
#pragma unroll
        for (int k = 0; k < NSTART; k++) s += kr[k] * Z[k * NN + n];
        g_Zc[c * NN + n] = s;
        g_Zold[c * NN + n] = s;
        g_X[0][c * XROW + 4 + n] = s + b0;
        g_X[1][c * XROW + 4 + n] = s + b1;
    }
}

// ---------------- Laplacian ----------------
__global__ void __launch_bounds__(256) k_sq() {
    int n = blockIdx.x * 64 + (threadIdx.x & 63);
    int cg = threadIdx.x >> 6;
    __shared__ float red[256];
    float s = 0.f;
#pragma unroll
    for (int c = cg * 32; c < cg * 32 + 32; c++) {
        float v = g_Zc[c * NN + n];
        s += v * v;
    }
    red[threadIdx.x] = s;
    __syncthreads();
    if (threadIdx.x < 64)
        g_sq[n] = red[threadIdx.x] + red[threadIdx.x + 64] + red[threadIdx.x + 128] + red[threadIdx.x + 192];
}

__global__ void __launch_bounds__(256) k_d2() {
    const int j0 = blockIdx.x * 64;
    const int i0 = blockIdx.y * 64;
    __shared__ float As[16 * 64];
    __shared__ float Bs[16 * 64];
    __shared__ float red[256];
    const int tid = threadIdx.x;
    const int tj = tid & 15, ti = tid >> 4;
    float acc[4][4] = {};
    for (int c = 0; c < 8; ++c) {
        int k0 = c * 16;
        for (int idx = tid; idx < 1024; idx += 256) {
            int k = idx >> 6, x = idx & 63;
            As[k * 64 + x] = g_Zc[(k0 + k) * NN + i0 + x];
            Bs[k * 64 + x] = g_Zc[(k0 + k) * NN + j0 + x];
        }
        __syncthreads();
#pragma unroll
        for (int kk = 0; kk < 16; ++kk) {
            float4 a = *(const float4*)&As[kk * 64 + ti * 4];
            float4 b = *(const float4*)&Bs[kk * 64 + tj * 4];
            acc[0][0] += a.x * b.x; acc[0][1] += a.x * b.y; acc[0][2] += a.x * b.z; acc[0][3] += a.x * b.w;
            acc[1][0] += a.y * b.x; acc[1][1] += a.y * b.y; acc[1][2] += a.y * b.z; acc[1][3] += a.y * b.w;
            acc[2][0] += a.z * b.x; acc[2][1] += a.z * b.y; acc[2][2] += a.z * b.z; acc[2][3] += a.z * b.w;
            acc[3][0] += a.w * b.x; acc[3][1] += a.w * b.y; acc[3][2] += a.w * b.z; acc[3][3] += a.w * b.w;
        }
        __syncthreads();
    }
    float lsum = 0.f;
#pragma unroll
    for (int r = 0; r < 4; ++r) {
        int i = i0 + ti * 4 + r;
        float sqi = g_sq[i];
        float4 o;
        float* po = (float*)&o;
#pragma unroll
        for (int cc = 0; cc < 4; ++cc) {
            int j = j0 + tj * 4 + cc;
            float d2 = fmaxf(sqi + g_sq[j] - 2.f * acc[r][cc], 0.f);
            po[cc] = d2;
            lsum += d2;
        }
        *(float4*)&g_W2[i * NN + j0 + tj * 4] = o;
    }
    red[tid] = lsum;
    __syncthreads();
    for (int o = 128; o > 0; o >>= 1) {
        if (tid < o) red[tid] += red[tid + o];
        __syncthreads();
    }
    if (tid == 0) g_part[blockIdx.y * 16 + blockIdx.x] = red[0];
}

__global__ void __launch_bounds__(256) k_sigma() {
    __shared__ float red[256];
    red[threadIdx.x] = g_part[threadIdx.x];
    __syncthreads();
    for (int o = 128; o > 0; o >>= 1) {
        if (threadIdx.x < o) red[threadIdx.x] += red[threadIdx.x + o];
        __syncthreads();
    }
    if (threadIdx.x == 0) g_sig = red[0];
}

__global__ void __launch_bounds__(256) k_wg() {
    int i = blockIdx.x;
    __shared__ float red[256];
    float sigma = g_sig * (1.f / 1048576.f) + 1e-12f;
    float inv = 1.f / sigma;
    float s = 0.f;
    for (int n = threadIdx.x; n < NN; n += 256) {
        float w = expf(-g_W2[i * NN + n] * inv);
        g_W2[i * NN + n] = w;
        s += w;
    }
    red[threadIdx.x] = s;
    __syncthreads();
    for (int o = 128; o > 0; o >>= 1) {
        if (threadIdx.x < o) red[threadIdx.x] += red[threadIdx.x + o];
        __syncthreads();
    }
    if (threadIdx.x == 0) g_deg[i] = red[0];
}

__global__ void __launch_bounds__(256) k_lap() {
    int i = blockIdx.x;
    float dhi = rsqrtf(g_deg[i]);
    for (int n = threadIdx.x; n < NN; n += 256) {
        float v = -dhi * rsqrtf(g_deg[n]) * g_W2[i * NN + n];
        if (n == i) v += 1.f;
        g_L[i * NN + n] = v;
    }
}

__global__ void __launch_bounds__(256) k_lapfm() {
    int idx = blockIdx.x * 256 + threadIdx.x;
    int k = idx >> 10, n = idx & 1023;
    float v = g_L[idx];
    int off = ((k >> 3) * 128 + (n >> 3)) * 64 + ((n & 7) * 4 + (k & 3)) * 2 + ((k & 7) >> 2);
    g_Lfm[off] = f2t(v);
}

// ---------------- forward conv (cp.async double-buffered) ----------------
// dyn smem: Xs[2][4224] @0, Asm[2][4608] @8448  (total 70656 B)
__global__ void __launch_bounds__(256) k_conv_mma(int layer) {
    extern __shared__ uint32_t dyn[];
    const int n0 = blockIdx.x * 256;
    const int mt = blockIdx.y;
    const int b = blockIdx.z >> 1, ch = blockIdx.z & 1;
    const int lb = layer * 2 + b;
    const int tid = threadIdx.x, lane = tid & 31, wrp = tid >> 5;
    const int wn0 = wrp * 32;
    const uint32_t smem_base = (uint32_t)__cvta_generic_to_shared(dyn);
    const float* xb = g_X[b] + n0;

    auto issue = [&](int cc, int s) {
        int ci0 = ch * 64 + cc * 16;
        uint32_t xs0 = smem_base + (s * 4224) * 4;
        for (int t = tid; t < 1056; t += 256) {
            int row = t / 66, q = t - row * 66;
            cp16(xs0 + (row * 264 + q * 4) * 4, xb + (ci0 + row) * XROW + q * 4);
        }
        const uint32_t* wsrc = g_Wc + ((size_t)((lb * 8 + mt) * 8 + ch * 4 + cc)) * 4608;
        uint32_t as0 = smem_base + (8448 + s * 4608) * 4;
        for (int t = tid; t < 1152; t += 256)
            cp16(as0 + t * 16, wsrc + t * 4);
    };

    float acc[2][4][4] = {};
    issue(0, 0); cp_commit();
    for (int cc = 0; cc < 4; ++cc) {
        int s = cc & 1;
        if (cc < 3) { issue(cc + 1, s ^ 1); cp_commit(); cp_wait1(); }
        else cp_wait0();
        __syncthreads();
        const uint32_t* XsS = dyn + s * 4224;
        const uint32_t* AsmS = dyn + 8448 + s * 4608;
#pragma unroll
        for (int j = 0; j < 9; ++j) {
#pragma unroll
            for (int cs = 0; cs < 2; ++cs) {
                int fb = ((j * 2 + cs) * 2) * 128 + lane * 4;
                uint32_t a0[4], a1[4];
                *(uint4*)a0 = *(const uint4*)&AsmS[fb];
                *(uint4*)a1 = *(const uint4*)&AsmS[fb + 128];
                int trow = cs * 8 + (lane & 3);
                int tb = wn0 + (lane >> 2) + j;
#pragma unroll
                for (int nf = 0; nf < 4; ++nf) {
                    uint32_t bb[2];
                    bb[0] = XsS[trow * 264 + tb + nf * 8];
                    bb[1] = XsS[(trow + 4) * 264 + tb + nf * 8];
                    mma8(acc[0][nf], a0, bb);
                    mma8(acc[1][nf], a1, bb);
                }
            }
        }
        __syncthreads();
    }
    float* H = g_H[b * 2 + ch];
    const int m0 = mt * 32;
#pragma unroll
    for (int mf = 0; mf < 2; ++mf)
#pragma unroll
        for (int nf = 0; nf < 4; ++nf) {
            int m = m0 + mf * 16 + (lane >> 2);
            int n = n0 + wn0 + nf * 8 + (lane & 3) * 2;
            *(float2*)&H[m * NN + n] = make_float2(acc[mf][nf][0], acc[mf][nf][1]);
            *(float2*)&H[(m + 8) * NN + n] = make_float2(acc[mf][nf][2], acc[mf][nf][3]);
        }
}

// ---------------- GEMM: P[kq] = H1 @ L  (double-buffered) ----------------
// dyn: As[2][1024] @0, Bs[2][8192] @2048  (total 73728 B)
__global__ void __launch_bounds__(256) k_gemmHL_mma() {
    extern __shared__ uint32_t dyn[];
    const int n0 = blockIdx.x * 256;
    const int m0 = blockIdx.y * 32;
    const int kq = blockIdx.z;
    const int tid = threadIdx.x, lane = tid & 31, wrp = tid >> 5;
    const int ngf0 = n0 >> 3;
    const uint32_t smem_base = (uint32_t)__cvta_generic_to_shared(dyn);

    auto prefA = [&](int cc, float* rv) {
        int k0 = kq * 256 + cc * 32;
#pragma unroll
        for (int u = 0; u < 4; ++u) {
            int idx = tid + u * 256;
            int m = idx >> 5, k = idx & 31;
            int off = (m0 + m) * NN + k0 + k;
            rv[u] = g_H[2][off] + g_H[3][off];
        }
    };
    auto stA = [&](int s, const float* rv) {
#pragma unroll
        for (int u = 0; u < 4; ++u) {
            int idx = tid + u * 256;
            int m = idx >> 5, k = idx & 31;
            int ks = k >> 3, kl = k & 7;
            int mf = m >> 4, row = m & 15;
            int ln = (row & 7) * 4 + (kl & 3);
            int e = (row >> 3) + ((kl >> 2) << 1);
            dyn[s * 1024 + ((ks * 2 + mf) * 32 + ln) * 4 + e] = __float_as_uint(rv[u]);
        }
    };
    auto issueB = [&](int cc, int s) {
        int k0 = kq * 256 + cc * 32;
        uint32_t bs0 = smem_base + (2048 + s * 8192) * 4;
        for (int idx = tid; idx < 2048; idx += 256) {
            int ks = idx >> 9, r = idx & 511;
            const uint4* src = (const uint4*)(g_Lfm + ((size_t)((k0 >> 3) + ks) * 128 + ngf0) * 64) + r;
            cp16(bs0 + idx * 16, src);
        }
    };

    float acc[2][4][4] = {};
    float rv[4], rv2[4];
    prefA(0, rv);
    issueB(0, 0); cp_commit();
    for (int cc = 0; cc < 8; ++cc) {
        int s = cc & 1;
        stA(s, rv);
        if (cc < 8 - 1) {
            issueB(cc + 1, s ^ 1); cp_commit();
            prefA(cc + 1, rv2);
            cp_wait1();
        } else cp_wait0();
        __syncthreads();
        const uint32_t* AsS = dyn + s * 1024;
        const uint32_t* BsS = dyn + 2048 + s * 8192;
#pragma unroll
        for (int ks = 0; ks < 4; ++ks) {
            uint32_t a0[4], a1[4];
            *(uint4*)a0 = *(const uint4*)&AsS[((ks * 2 + 0) * 32 + lane) * 4];
            *(uint4*)a1 = *(const uint4*)&AsS[((ks * 2 + 1) * 32 + lane) * 4];
#pragma unroll
            for (int nf = 0; nf < 4; ++nf) {
                uint32_t bb[2];
                *(uint2*)bb = *(const uint2*)&BsS[((ks * 32 + wrp * 4 + nf) * 32 + lane) * 2];
                mma8(acc[0][nf], a0, bb);
                mma8(acc[1][nf], a1, bb);
            }
        }
        __syncthreads();
#pragma unroll
        for (int u = 0; u < 4; ++u) rv[u] = rv2[u];
    }
    float* P = g_P[kq];
#pragma unroll
    for (int mf = 0; mf < 2; ++mf)
#pragma unroll
        for (int nf = 0; nf < 4; ++nf) {
            int m = m0 + mf * 16 + (lane >> 2);
            int n = n0 + wrp * 32 + nf * 8 + (lane & 3) * 2;
            *(float2*)&P[m * NN + n] = make_float2(acc[mf][nf][0], acc[mf][nf][1]);
            *(float2*)&P[(m + 8) * NN + n] = make_float2(acc[mf][nf][2], acc[mf][nf][3]);
        }
}

// ---------------- stats + Y precompute (fused) ----------------
__global__ void __launch_bounds__(256) k_statsY() {
    int ch = blockIdx.x;
    int b = ch >> 8, c = ch & 255;
    __shared__ float row[1024];
    __shared__ float rs[256], rs2[256];
    float s = 0.f, s2 = 0.f;
    if (b == 0) {
        const float* p0 = &g_H[0][c * NN];
        const float* p1 = &g_H[1][c * NN];
        for (int n = threadIdx.x; n < NN; n += 256) {
            float v = p0[n] + p1[n];
            row[n] = v; s += v; s2 += v * v;
        }
    } else {
        const float* p0 = &g_P[0][c * NN];
        const float* p1 = &g_P[1][c * NN];
        const float* p2 = &g_P[2][c * NN];
        const float* p3 = &g_P[3][c * NN];
        for (int n = threadIdx.x; n < NN; n += 256) {
            float v = p0[n] + p1[n] + p2[n] + p3[n];
            row[n] = v; s += v; s2 += v * v;
        }
    }
    rs[threadIdx.x] = s; rs2[threadIdx.x] = s2;
    __syncthreads();
    for (int o = 128; o > 0; o >>= 1) {
        if (threadIdx.x < o) { rs[threadIdx.x] += rs[threadIdx.x + o]; rs2[threadIdx.x] += rs2[threadIdx.x + o]; }
        __syncthreads();
    }
    float mean = rs[0] * (1.f / NN);
    float var = rs2[0] * (1.f / NN) - mean * mean;
    float rstd = rsqrtf(var + 1e-5f);
    float* y = &g_Y[b][c * XROW + 4];
    for (int n = threadIdx.x; n < NN; n += 256)
        y[n] = fmaxf((row[n] - mean) * rstd, 0.f);
}

// ---------------- transposed conv (cp.async double-buffered) ----------------
__global__ void __launch_bounds__(256) k_convT_mma(int layer) {
    extern __shared__ uint32_t dyn[];
    const int n0 = blockIdx.x * 256;
    const int mt = blockIdx.y;
    const int b = blockIdx.z >> 2, q = blockIdx.z & 3;
    const int lb = layer * 2 + b;
    const int tid = threadIdx.x, lane = tid & 31, wrp = tid >> 5;
    const int wn0 = wrp * 32;
    const uint32_t smem_base = (uint32_t)__cvta_generic_to_shared(dyn);
    const float* yb = g_Y[b] + n0;

    auto issue = [&](int cc, int s) {
        int chunk = q * 4 + cc;
        int co0 = chunk * 16;
        uint32_t ys0 = smem_base + (s * 4224) * 4;
        for (int t = tid; t < 1056; t += 256) {
            int row = t / 66, qq = t - row * 66;
            cp16(ys0 + (row * 264 + qq * 4) * 4, yb + (co0 + row) * XROW + qq * 4);
        }
        const uint32_t* wsrc = g_Wt + ((size_t)((lb * 4 + mt) * 16 + chunk)) * 4608;
        uint32_t as0 = smem_base + (8448 + s * 4608) * 4;
        for (int t = tid; t < 1152; t += 256)
            cp16(as0 + t * 16, wsrc + t * 4);
    };

    float acc[2][4][4] = {};
    issue(0, 0); cp_commit();
    for (int cc = 0; cc < 4; ++cc) {
        int s = cc & 1;
        if (cc < 3) { issue(cc + 1, s ^ 1); cp_commit(); cp_wait1(); }
        else cp_wait0();
        __syncthreads();
        const uint32_t* YsS = dyn + s * 4224;
        const uint32_t* AsmS = dyn + 8448 + s * 4608;
#pragma unroll
        for (int j = 0; j < 9; ++j) {
#pragma unroll
            for (int cs = 0; cs < 2; ++cs) {
                int fb = ((j * 2 + cs) * 2) * 128 + lane * 4;
                uint32_t a0[4], a1[4];
                *(uint4*)a0 = *(const uint4*)&AsmS[fb];
                *(uint4*)a1 = *(const uint4*)&AsmS[fb + 128];
                int trow = cs * 8 + (lane & 3);
                int tb = wn0 + (lane >> 2) + (8 - j);
#pragma unroll
                for (int nf = 0; nf < 4; ++nf) {
                    uint32_t bb[2];
                    bb[0] = YsS[trow * 264 + tb + nf * 8];
                    bb[1] = YsS[(trow + 4) * 264 + tb + nf * 8];
                    mma8(acc[0][nf], a0, bb);
                    mma8(acc[1][nf], a1, bb);
                }
            }
        }
        __syncthreads();
    }
    float* T = g_T[b * 4 + q];
    const int m0 = mt * 32;
#pragma unroll
    for (int mf = 0; mf < 2; ++mf)
#pragma unroll
        for (int nf = 0; nf < 4; ++nf) {
            int m = m0 + mf * 16 + (lane >> 2);
            int n = n0 + wn0 + nf * 8 + (lane & 3) * 2;
            *(float2*)&T[m * NN + n] = make_float2(acc[mf][nf][0], acc[mf][nf][1]);
            *(float2*)&T[(m + 8) * NN + n] = make_float2(acc[mf][nf][2], acc[mf][nf][3]);
        }
}

// ---------------- GEMM: Q[kq] = T1 @ L  (double-buffered) ----------------
__global__ void __launch_bounds__(256) k_gemmQ_mma() {
    extern __shared__ uint32_t dyn[];
    const int n0 = blockIdx.x * 256;
    const int m0 = blockIdx.y * 32;
    const int kq = blockIdx.z;
    const int tid = threadIdx.x, lane = tid & 31, wrp = tid >> 5;
    const int ngf0 = n0 >> 3;
    const uint32_t smem_base = (uint32_t)__cvta_generic_to_shared(dyn);

    auto prefA = [&](int cc, float* rv) {
        int k0 = kq * 128 + cc * 32;
#pragma unroll
        for (int u = 0; u < 4; ++u) {
            int idx = tid + u * 256;
            int m = idx >> 5, k = idx & 31;
            int off = (m0 + m) * NN + k0 + k;
            rv[u] = g_T[4][off] + g_T[5][off] + g_T[6][off] + g_T[7][off];
        }
    };
    auto stA = [&](int s, const float* rv) {
#pragma unroll
        for (int u = 0; u < 4; ++u) {
            int idx = tid + u * 256;
            int m = idx >> 5, k = idx & 31;
            int ks = k >> 3, kl = k & 7;
            int mf = m >> 4, row = m & 15;
            int ln = (row & 7) * 4 + (kl & 3);
            int e = (row >> 3) + ((kl >> 2) << 1);
            dyn[s * 1024 + ((ks * 2 + mf) * 32 + ln) * 4 + e] = __float_as_uint(rv[u]);
        }
    };
    auto issueB = [&](int cc, int s) {
        int k0 = kq * 128 + cc * 32;
        uint32_t bs0 = smem_base + (2048 + s * 8192) * 4;
        for (int idx = tid; idx < 2048; idx += 256) {
            int ks = idx >> 9, r = idx & 511;
            const uint4* src = (const uint4*)(g_Lfm + ((size_t)((k0 >> 3) + ks) * 128 + ngf0) * 64) + r;
            cp16(bs0 + idx * 16, src);
        }
    };

    float acc[2][4][4] = {};
    float rv[4], rv2[4];
    prefA(0, rv);
    issueB(0, 0); cp_commit();
    for (int cc = 0; cc < 4; ++cc) {
        int s = cc & 1;
        stA(s, rv);
        if (cc < 3) {
            issueB(cc + 1, s ^ 1); cp_commit();
            prefA(cc + 1, rv2);
            cp_wait1();
        } else cp_wait0();
        __syncthreads();
        const uint32_t* AsS = dyn + s * 1024;
        const uint32_t* BsS = dyn + 2048 + s * 8192;
#pragma unroll
        for (int ks = 0; ks < 4; ++ks) {
            uint32_t a0[4], a1[4];
            *(uint4*)a0 = *(const uint4*)&AsS[((ks * 2 + 0) * 32 + lane) * 4];
            *(uint4*)a1 = *(const uint4*)&AsS[((ks * 2 + 1) * 32 + lane) * 4];
#pragma unroll
            for (int nf = 0; nf < 4; ++nf) {
                uint32_t bb[2];
                *(uint2*)bb = *(const uint2*)&BsS[((ks * 32 + wrp * 4 + nf) * 32 + lane) * 2];
                mma8(acc[0][nf], a0, bb);
                mma8(acc[1][nf], a1, bb);
            }
        }
        __syncthreads();
#pragma unroll
        for (int u = 0; u < 4; ++u) rv[u] = rv2[u];
    }
    float* Q = g_Q[kq];
#pragma unroll
    for (int mf = 0; mf < 2; ++mf)
#pragma unroll
        for (int nf = 0; nf < 4; ++nf) {
            int m = m0 + mf * 16 + (lane >> 2);
            int n = n0 + wrp * 32 + nf * 8 + (lane & 3) * 2;
            *(float2*)&Q[m * NN + n] = make_float2(acc[mf][nf][0], acc[mf][nf][1]);
            *(float2*)&Q[(m + 8) * NN + n] = make_float2(acc[mf][nf][2], acc[mf][nf][3]);
        }
}

// ---------------- leapfrog update + next-layer X precompute ----------------
__global__ void __launch_bounds__(256) k_update(const float* __restrict__ Bias, int layer) {
    int idx = blockIdx.x * 256 + threadIdx.x;
    int base = idx * 4;
    int c = base >> 10, n = base & 1023;
    float4 a0 = *(const float4*)&g_T[0][base];
    float4 a1 = *(const float4*)&g_T[1][base];
    float4 a2 = *(const float4*)&g_T[2][base];
    float4 a3 = *(const float4*)&g_T[3][base];
    float sx = a0.x + a1.x + a2.x + a3.x;
    float sy = a0.y + a1.y + a2.y + a3.y;
    float sz = a0.z + a1.z + a2.z + a3.z;
    float sw = a0.w + a1.w + a2.w + a3.w;
#pragma unroll
    for (int qq = 0; qq < 8; ++qq) {
        float4 t = *(const float4*)&g_Q[qq][base];
        sx += t.x; sy += t.y; sz += t.z; sw += t.w;
    }
    float4 zc = *(const float4*)&g_Zc[base];
    float4 zo = *(const float4*)&g_Zold[base];
    float4 zn;
    zn.x = 2.f * zc.x - zo.x - 0.01f * sx;
    zn.y = 2.f * zc.y - zo.y - 0.01f * sy;
    zn.z = 2.f * zc.z - zo.z - 0.01f * sz;
    zn.w = 2.f * zc.w - zo.w - 0.01f * sw;
    *(float4*)&g_Zold[base] = zc;
    *(float4*)&g_Zc[base] = zn;
    if (layer + 1 < NLAYERS) {
        float b0 = Bias[((layer + 1) * 2 + 0) * NOPEN + c];
        float b1 = Bias[((layer + 1) * 2 + 1) * NOPEN + c];
        float4 x0 = make_float4(zn.x + b0, zn.y + b0, zn.z + b0, zn.w + b0);
        float4 x1 = make_float4(zn.x + b1, zn.y + b1, zn.z + b1, zn.w + b1);
        *(float4*)&g_X[0][c * XROW + 4 + n] = x0;
        *(float4*)&g_X[1][c * XROW + 4 + n] = x1;
    }
}

// ---------------- output ----------------
__global__ void __launch_bounds__(256) k_out(const float* __restrict__ Kclose,
                                             float* __restrict__ out) {
    int r = blockIdx.x % 3, sel = blockIdx.x / 3;
    const float* src = sel ? g_Zold : g_Zc;
    __shared__ float kc[NOPEN];
    if (threadIdx.x < NOPEN) kc[threadIdx.x] = Kclose[r * NOPEN + threadIdx.x];
    __syncthreads();
    for (int n = threadIdx.x; n < NN; n += 256) {
        float s = 0.f;
#pragma unroll 8
        for (int k = 0; k < NOPEN; k++) s += kc[k] * src[k * NN + n];
        out[sel * (NCLOSE * NN) + r * NN + n] = s;
    }
}

// ---------------- host ----------------
extern "C" void kernel_launch(void* const* d_in, const int* in_sizes, int n_in,
                              void* d_out, int out_size) {
    const float* Z      = (const float*)d_in[0];
    const float* Kopen  = (const float*)d_in[1];
    const float* Kclose = (const float*)d_in[2];
    const float* W      = (const float*)d_in[3];
    const float* Bias   = (const float*)d_in[4];
    float* out = (float*)d_out;

    const int SM_CONV = 70656, SM_GEMM = 73728;
    cudaFuncSetAttribute(k_conv_mma, cudaFuncAttributeMaxDynamicSharedMemorySize, SM_CONV);
    cudaFuncSetAttribute(k_convT_mma, cudaFuncAttributeMaxDynamicSharedMemorySize, SM_CONV);
    cudaFuncSetAttribute(k_gemmHL_mma, cudaFuncAttributeMaxDynamicSharedMemorySize, SM_GEMM);
    cudaFuncSetAttribute(k_gemmQ_mma, cudaFuncAttributeMaxDynamicSharedMemorySize, SM_GEMM);

    k_wfmt_conv<<<5120, 256>>>(W);        // 0
    k_wfmt_convT<<<5120, 256>>>(W);       // 1
    k_init<<<128, 256>>>(Z, Kopen, Bias); // 2
    for (int i = 0; i < NLAYERS; i++) {
        if (i == 0) {
            k_sq<<<16, 256>>>();                               // 3
            k_d2<<<dim3(16, 16), 256>>>();                     // 4
            k_conv_mma<<<dim3(4, 8, 4), 256, SM_CONV>>>(i);    // 5  <- profiled
            k_sigma<<<1, 256>>>();
            k_wg<<<1024, 256>>>();
            k_lap<<<1024, 256>>>();
            k_lapfm<<<4096, 256>>>();
        } else if (i % 10 == 0) {
            k_conv_mma<<<dim3(4, 8, 4), 256, SM_CONV>>>(i);
            k_sq<<<16, 256>>>();
            k_d2<<<dim3(16, 16), 256>>>();
            k_sigma<<<1, 256>>>();
            k_wg<<<1024, 256>>>();
            k_lap<<<1024, 256>>>();
            k_lapfm<<<4096, 256>>>();
        } else {
            k_conv_mma<<<dim3(4, 8, 4), 256, SM_CONV>>>(i);
        }
        k_gemmHL_mma<<<dim3(4, 8, 4), 256, SM_GEMM>>>();
        k_statsY<<<512, 256>>>();
        k_convT_mma<<<dim3(4, 4, 8), 256, SM_CONV>>>(i);
        k_gemmQ_mma<<<dim3(4, 4, 8), 256, SM_GEMM>>>();
        k_update<<<128, 256>>>(Bias, i);
    }
    k_out<<<6, 256>>>(Kclose, out);
}

// round 7
// speedup vs baseline: 5.2146x; 1.1754x over previous
#include <cuda_runtime.h>
#include <cuda_bf16.h>
#include <cstdint>

#define NSTART 40
#define NOPEN 128
#define NHID 256
#define NCLOSE 3
#define NLAYERS 40
#define NN 1024
#define XROW 1032   // packed uint32 row: 4 halo + 1024 + 4 halo

// ---------------- device scratch ----------------
__device__ __align__(16) float g_Zc[NOPEN * NN];
__device__ __align__(16) float g_Zold[NOPEN * NN];
__device__ __align__(16) float g_L[NN * NN];
__device__ __align__(16) uint32_t g_Lfm[64 * 128 * 64];   // bf16x2 B-frags [kg][ng][lane][2]
__device__ __align__(16) float g_W2[NN * NN];
__device__ float g_deg[NN];
__device__ float g_sq[NN];
__device__ float g_part[256];
__device__ float g_sig;
__device__ __align__(16) float g_H[4][NHID * NN];   // conv partials [b*2+ci_half]
__device__ __align__(16) float g_P[4][NHID * NN];   // H1@L partials [k-quarter]
__device__ __align__(16) float g_T[8][NOPEN * NN];  // convT partials [b*4+co_quarter]
__device__ __align__(16) float g_Q[8][NOPEN * NN];  // T1@L partials [k-eighth]
__device__ __align__(16) uint32_t g_Xp[2][64 * XROW];    // (Zc+bias) bf16x2 channel pairs, halo'd
__device__ __align__(16) uint32_t g_Yp[2][128 * XROW];   // relu(norm) bf16x2 channel pairs
__device__ __align__(16) uint32_t g_Wc[5120 * 2304];     // conv A-frags bf16
__device__ __align__(16) uint32_t g_Wt[5120 * 2304];     // convT A-frags bf16

// ---------------- helpers ----------------
__device__ __forceinline__ uint32_t pk(float a, float b) {
    __nv_bfloat162 v = __floats2bfloat162_rn(a, b);
    return *reinterpret_cast<uint32_t*>(&v);
}
__device__ __forceinline__ void mma16(float* d, const uint32_t* a, const uint32_t* b) {
    asm volatile(
        "mma.sync.aligned.m16n8k16.row.col.f32.bf16.bf16.f32 "
        "{%0,%1,%2,%3}, {%4,%5,%6,%7}, {%8,%9}, {%0,%1,%2,%3};"
        : "+f"(d[0]), "+f"(d[1]), "+f"(d[2]), "+f"(d[3])
        : "r"(a[0]), "r"(a[1]), "r"(a[2]), "r"(a[3]), "r"(b[0]), "r"(b[1]));
}
__device__ __forceinline__ void cp16(uint32_t smem, const void* gmem) {
    asm volatile("cp.async.cg.shared.global [%0], [%1], 16;\n" :: "r"(smem), "l"(gmem));
}
__device__ __forceinline__ void cp_commit() { asm volatile("cp.async.commit_group;\n"); }
__device__ __forceinline__ void cp_wait1() { asm volatile("cp.async.wait_group 1;\n"); }
__device__ __forceinline__ void cp_wait0() { asm volatile("cp.async.wait_group 0;\n"); }

// ---------------- weight preformat (bf16 pair fragments) ----------------
__global__ void __launch_bounds__(256) k_wfmt_conv(const float* __restrict__ W) {
    int bid = blockIdx.x;                       // (lb*8 + mt)*8 + cc8
    int cc8 = bid & 7, mt = (bid >> 3) & 7, lb = bid >> 6;
    __shared__ float Ws[4608];                  // [co_l(32)][ci_l(16)][j(9)]
    const float* src = W + ((size_t)lb * 256 + mt * 32) * 1152 + cc8 * 144;
    for (int idx = threadIdx.x; idx < 4608; idx += 256) {
        int co_l = idx / 144, r = idx - co_l * 144;
        Ws[idx] = src[(size_t)co_l * 1152 + r];
    }
    __syncthreads();
    uint32_t* dst = g_Wc + (size_t)bid * 2304;
    for (int o = threadIdx.x; o < 2304; o += 256) {
        int r = o & 3, lane = (o >> 2) & 31, mf = (o >> 7) & 1, j = o >> 8;
        int t2 = lane & 3, g = lane >> 2;
        int co_l = mf * 16 + (r & 1) * 8 + g;
        int ci_l = ((r >> 1) & 1) * 8 + 2 * t2;
        dst[o] = pk(Ws[co_l * 144 + ci_l * 9 + j], Ws[co_l * 144 + (ci_l + 1) * 9 + j]);
    }
}

__global__ void __launch_bounds__(256) k_wfmt_convT(const float* __restrict__ W) {
    int bid = blockIdx.x;                       // (lb*4 + mt)*16 + chunk
    int chunk = bid & 15, mt = (bid >> 4) & 3, lb = bid >> 6;
    __shared__ float Ws[4608];                  // [co_l(16)][ci_l(32)][j(9)]
    const float* src = W + ((size_t)lb * 256 + chunk * 16) * 1152 + mt * 288;
    for (int idx = threadIdx.x; idx < 4608; idx += 256) {
        int co_l = idx / 288, r = idx - co_l * 288;
        Ws[idx] = src[(size_t)co_l * 1152 + r];
    }
    __syncthreads();
    uint32_t* dst = g_Wt + (size_t)bid * 2304;
    for (int o = threadIdx.x; o < 2304; o += 256) {
        int r = o & 3, lane = (o >> 2) & 31, mf = (o >> 7) & 1, j = o >> 8;
        int t2 = lane & 3, g = lane >> 2;
        int ci_l = mf * 16 + (r & 1) * 8 + g;      // m dim
        int co_l = ((r >> 1) & 1) * 8 + 2 * t2;    // k dim (pairs)
        dst[o] = pk(Ws[co_l * 288 + ci_l * 9 + j], Ws[(co_l + 1) * 288 + ci_l * 9 + j]);
    }
}

// ---------------- init: Zc = Kopen @ Z ; Zold = Zc ; Xp for layer 0 ----------------
__global__ void __launch_bounds__(256) k_init(const float* __restrict__ Z,
                                              const float* __restrict__ Kopen,
                                              const float* __restrict__ Bias) {
    int c2 = blockIdx.x;   // 0..63 channel pairs
    __shared__ float kr[80];
    if (threadIdx.x < 80) {
        int c = 2 * c2 + threadIdx.x / 40;
        kr[threadIdx.x] = Kopen[c * NSTART + (threadIdx.x % 40)];
    }
    __syncthreads();
    float b00 = Bias[2 * c2], b01 = Bias[2 * c2 + 1];
    float b10 = Bias[NOPEN + 2 * c2], b11 = Bias[NOPEN + 2 * c2 + 1];
    for (int n = threadIdx.x; n < NN; n += 256) {
        float s0 = 0.f, s1 = 0.f;
#pragma unroll
        for (int k = 0; k < NSTART; k++) {
            float z = Z[k * NN + n];
            s0 += kr[k] * z;
            s1 += kr[40 + k] * z;
        }
        g_Zc[(2 * c2) * NN + n] = s0;  g_Zold[(2 * c2) * NN + n] = s0;
        g_Zc[(2 * c2 + 1) * NN + n] = s1; g_Zold[(2 * c2 + 1) * NN + n] = s1;
        g_Xp[0][c2 * XROW + 4 + n] = pk(s0 + b00, s1 + b01);
        g_Xp[1][c2 * XROW + 4 + n] = pk(s0 + b10, s1 + b11);
    }
}

// ---------------- Laplacian ----------------
__global__ void __launch_bounds__(256) k_sq() {
    int n = blockIdx.x * 64 + (threadIdx.x & 63);
    int cg = threadIdx.x >> 6;
    __shared__ float red[256];
    float s = 0.f;
#pragma unroll
    for (int c = cg * 32; c < cg * 32 + 32; c++) {
        float v = g_Zc[c * NN + n];
        s += v * v;
    }
    red[threadIdx.x] = s;
    __syncthreads();
    if (threadIdx.x < 64)
        g_sq[n] = red[threadIdx.x] + red[threadIdx.x + 64] + red[threadIdx.x + 128] + red[threadIdx.x + 192];
}

__global__ void __launch_bounds__(256) k_d2() {
    const int j0 = blockIdx.x * 64;
    const int i0 = blockIdx.y * 64;
    __shared__ float As[16 * 64];
    __shared__ float Bs[16 * 64];
    __shared__ float red[256];
    const int tid = threadIdx.x;
    const int tj = tid & 15, ti = tid >> 4;
    float acc[4][4] = {};
    for (int c = 0; c < 8; ++c) {
        int k0 = c * 16;
        for (int idx = tid; idx < 1024; idx += 256) {
            int k = idx >> 6, x = idx & 63;
            As[k * 64 + x] = g_Zc[(k0 + k) * NN + i0 + x];
            Bs[k * 64 + x] = g_Zc[(k0 + k) * NN + j0 + x];
        }
        __syncthreads();
#pragma unroll
        for (int kk = 0; kk < 16; ++kk) {
            float4 a = *(const float4*)&As[kk * 64 + ti * 4];
            float4 b = *(const float4*)&Bs[kk * 64 + tj * 4];
            acc[0][0] += a.x * b.x; acc[0][1] += a.x * b.y; acc[0][2] += a.x * b.z; acc[0][3] += a.x * b.w;
            acc[1][0] += a.y * b.x; acc[1][1] += a.y * b.y; acc[1][2] += a.y * b.z; acc[1][3] += a.y * b.w;
            acc[2][0] += a.z * b.x; acc[2][1] += a.z * b.y; acc[2][2] += a.z * b.z; acc[2][3] += a.z * b.w;
            acc[3][0] += a.w * b.x; acc[3][1] += a.w * b.y; acc[3][2] += a.w * b.z; acc[3][3] += a.w * b.w;
        }
        __syncthreads();
    }
    float lsum = 0.f;
#pragma unroll
    for (int r = 0; r < 4; ++r) {
        int i = i0 + ti * 4 + r;
        float sqi = g_sq[i];
        float4 o;
        float* po = (float*)&o;
#pragma unroll
        for (int cc = 0; cc < 4; ++cc) {
            int j = j0 + tj * 4 + cc;
            float d2 = fmaxf(sqi + g_sq[j] - 2.f * acc[r][cc], 0.f);
            po[cc] = d2;
            lsum += d2;
        }
        *(float4*)&g_W2[i * NN + j0 + tj * 4] = o;
    }
    red[tid] = lsum;
    __syncthreads();
    for (int o = 128; o > 0; o >>= 1) {
        if (tid < o) red[tid] += red[tid + o];
        __syncthreads();
    }
    if (tid == 0) g_part[blockIdx.y * 16 + blockIdx.x] = red[0];
}

__global__ void __launch_bounds__(256) k_sigma() {
    __shared__ float red[256];
    red[threadIdx.x] = g_part[threadIdx.x];
    __syncthreads();
    for (int o = 128; o > 0; o >>= 1) {
        if (threadIdx.x < o) red[threadIdx.x] += red[threadIdx.x + o];
        __syncthreads();
    }
    if (threadIdx.x == 0) g_sig = red[0];
}

__global__ void __launch_bounds__(256) k_wg() {
    int i = blockIdx.x;
    __shared__ float red[256];
    float sigma = g_sig * (1.f / 1048576.f) + 1e-12f;
    float inv = 1.f / sigma;
    float s = 0.f;
    for (int n = threadIdx.x; n < NN; n += 256) {
        float w = expf(-g_W2[i * NN + n] * inv);
        g_W2[i * NN + n] = w;
        s += w;
    }
    red[threadIdx.x] = s;
    __syncthreads();
    for (int o = 128; o > 0; o >>= 1) {
        if (threadIdx.x < o) red[threadIdx.x] += red[threadIdx.x + o];
        __syncthreads();
    }
    if (threadIdx.x == 0) g_deg[i] = red[0];
}

__global__ void __launch_bounds__(256) k_lap() {
    int i = blockIdx.x;
    float dhi = rsqrtf(g_deg[i]);
    for (int n = threadIdx.x; n < NN; n += 256) {
        float v = -dhi * rsqrtf(g_deg[n]) * g_W2[i * NN + n];
        if (n == i) v += 1.f;
        g_L[i * NN + n] = v;
    }
}

// L -> bf16 B-fragment layout: [kg(64)][ng(128)][lane(32)][2]
__global__ void __launch_bounds__(256) k_lapfm() {
    int idx = blockIdx.x * 256 + threadIdx.x;  // grid 1024 -> 262144
    int lane = idx & 31, ng = (idx >> 5) & 127, kg = idx >> 12;
    int t2 = lane & 3, g = lane >> 2;
    int n = ng * 8 + g;
    int k0 = kg * 16 + 2 * t2;
    uint32_t b0 = pk(g_L[k0 * NN + n], g_L[(k0 + 1) * NN + n]);
    uint32_t b1 = pk(g_L[(k0 + 8) * NN + n], g_L[(k0 + 9) * NN + n]);
    g_Lfm[((size_t)(kg * 128 + ng)) * 64 + lane * 2] = b0;
    g_Lfm[((size_t)(kg * 128 + ng)) * 64 + lane * 2 + 1] = b1;
}

// ---------------- forward conv (bf16 m16n8k16, cp.async double-buffered) ----------------
// dyn: Xs[2][2112] @0, Asm[2][2304] @4224  (35328 B)
__global__ void __launch_bounds__(256) k_conv_mma(int layer) {
    extern __shared__ uint32_t dyn[];
    const int n0 = blockIdx.x * 256;
    const int mt = blockIdx.y;
    const int b = blockIdx.z >> 1, ch = blockIdx.z & 1;
    const int lb = layer * 2 + b;
    const int tid = threadIdx.x, lane = tid & 31, wrp = tid >> 5;
    const int wn0 = wrp * 32;
    const uint32_t smem_base = (uint32_t)__cvta_generic_to_shared(dyn);
    const uint32_t* xb = g_Xp[b] + n0;

    auto issue = [&](int cc, int s) {
        int c2b = ch * 32 + cc * 8;
        uint32_t xs0 = smem_base + (s * 2112) * 4;
        for (int t = tid; t < 528; t += 256) {
            int row = t / 66, q = t - row * 66;
            cp16(xs0 + (row * 264 + q * 4) * 4, xb + (c2b + row) * XROW + q * 4);
        }
        const uint32_t* wsrc = g_Wc + ((size_t)((lb * 8 + mt) * 8 + ch * 4 + cc)) * 2304;
        uint32_t as0 = smem_base + (4224 + s * 2304) * 4;
        for (int t = tid; t < 576; t += 256)
            cp16(as0 + t * 16, wsrc + t * 4);
    };

    float acc[2][4][4] = {};
    issue(0, 0); cp_commit();
    for (int cc = 0; cc < 4; ++cc) {
        int s = cc & 1;
        if (cc < 3) { issue(cc + 1, s ^ 1); cp_commit(); cp_wait1(); }
        else cp_wait0();
        __syncthreads();
        const uint32_t* XsS = dyn + s * 2112;
        const uint32_t* AsmS = dyn + 4224 + s * 2304;
        const int r0 = (lane & 3) * 264, r1 = r0 + 4 * 264;
#pragma unroll
        for (int j = 0; j < 9; ++j) {
            uint32_t a0[4], a1[4];
            *(uint4*)a0 = *(const uint4*)&AsmS[(j * 2 + 0) * 128 + lane * 4];
            *(uint4*)a1 = *(const uint4*)&AsmS[(j * 2 + 1) * 128 + lane * 4];
            int tb = wn0 + (lane >> 2) + j;
#pragma unroll
            for (int nf = 0; nf < 4; ++nf) {
                uint32_t bb[2];
                bb[0] = XsS[r0 + tb + nf * 8];
                bb[1] = XsS[r1 + tb + nf * 8];
                mma16(acc[0][nf], a0, bb);
                mma16(acc[1][nf], a1, bb);
            }
        }
        __syncthreads();
    }
    float* H = g_H[b * 2 + ch];
    const int m0 = mt * 32;
#pragma unroll
    for (int mf = 0; mf < 2; ++mf)
#pragma unroll
        for (int nf = 0; nf < 4; ++nf) {
            int m = m0 + mf * 16 + (lane >> 2);
            int n = n0 + wn0 + nf * 8 + (lane & 3) * 2;
            *(float2*)&H[m * NN + n] = make_float2(acc[mf][nf][0], acc[mf][nf][1]);
            *(float2*)&H[(m + 8) * NN + n] = make_float2(acc[mf][nf][2], acc[mf][nf][3]);
        }
}

// ---------------- GEMM: P[kq] = H1 @ L (bf16, double-buffered) ----------------
// dyn: As[2][512] @0, Bs[2][4096] @1024  (36864 B)
__global__ void __launch_bounds__(256) k_gemmHL_mma() {
    extern __shared__ uint32_t dyn[];
    const int n0 = blockIdx.x * 256;
    const int m0 = blockIdx.y * 32;
    const int kq = blockIdx.z;  // 0..3
    const int tid = threadIdx.x, lane = tid & 31, wrp = tid >> 5;
    const uint32_t smem_base = (uint32_t)__cvta_generic_to_shared(dyn);

    auto prefA = [&](int cc, float* rv) {
        int k0 = kq * 256 + cc * 32;
#pragma unroll
        for (int u = 0; u < 2; ++u) {
            int idx = tid + u * 256;
            int r = idx & 3, ln = (idx >> 2) & 31, mf = (idx >> 7) & 1, kg = idx >> 8;
            int m = m0 + mf * 16 + (r & 1) * 8 + (ln >> 2);
            int k = k0 + kg * 16 + ((r >> 1) & 1) * 8 + 2 * (ln & 3);
            int off = m * NN + k;
            rv[u * 2] = g_H[2][off] + g_H[3][off];
            rv[u * 2 + 1] = g_H[2][off + 1] + g_H[3][off + 1];
        }
    };
    auto stA = [&](int s, const float* rv) {
#pragma unroll
        for (int u = 0; u < 2; ++u)
            dyn[s * 512 + tid + u * 256] = pk(rv[u * 2], rv[u * 2 + 1]);
    };
    auto issueB = [&](int cc, int s) {
        int kgb = kq * 16 + cc * 2;
        uint32_t bs0 = smem_base + (1024 + s * 4096) * 4;
        for (int t = tid; t < 1024; t += 256) {
            int kg = t >> 9, r = t & 511;
            cp16(bs0 + (kg * 2048 + r * 4) * 4,
                 g_Lfm + ((size_t)(kgb + kg) * 128 + (n0 >> 3)) * 64 + r * 4);
        }
    };

    float acc[2][4][4] = {};
    float rv[4], rv2[4];
    prefA(0, rv);
    issueB(0, 0); cp_commit();
    for (int cc = 0; cc < 8; ++cc) {
        int s = cc & 1;
        stA(s, rv);
        if (cc < 7) {
            issueB(cc + 1, s ^ 1); cp_commit();
            prefA(cc + 1, rv2);
            cp_wait1();
        } else cp_wait0();
        __syncthreads();
        const uint32_t* AsS = dyn + s * 512;
        const uint32_t* BsS = dyn + 1024 + s * 4096;
#pragma unroll
        for (int kg = 0; kg < 2; ++kg) {
            uint32_t a0[4], a1[4];
            *(uint4*)a0 = *(const uint4*)&AsS[(kg * 2 + 0) * 128 + lane * 4];
            *(uint4*)a1 = *(const uint4*)&AsS[(kg * 2 + 1) * 128 + lane * 4];
#pragma unroll
            for (int nf = 0; nf < 4; ++nf) {
                uint32_t bb[2];
                *(uint2*)bb = *(const uint2*)&BsS[kg * 2048 + (wrp * 4 + nf) * 64 + lane * 2];
                mma16(acc[0][nf], a0, bb);
                mma16(acc[1][nf], a1, bb);
            }
        }
        __syncthreads();
#pragma unroll
        for (int u = 0; u < 4; ++u) rv[u] = rv2[u];
    }
    float* P = g_P[kq];
#pragma unroll
    for (int mf = 0; mf < 2; ++mf)
#pragma unroll
        for (int nf = 0; nf < 4; ++nf) {
            int m = m0 + mf * 16 + (lane >> 2);
            int n = n0 + wrp * 32 + nf * 8 + (lane & 3) * 2;
            *(float2*)&P[m * NN + n] = make_float2(acc[mf][nf][0], acc[mf][nf][1]);
            *(float2*)&P[(m + 8) * NN + n] = make_float2(acc[mf][nf][2], acc[mf][nf][3]);
        }
}

// ---------------- stats + packed Y precompute ----------------
__global__ void __launch_bounds__(256) k_statsY() {
    int chp = blockIdx.x;   // 0..255: b*128 + c2
    int b = chp >> 7, c2 = chp & 127;
    __shared__ float row0[1024], row1[1024];
    __shared__ float rs0[256], rq0[256], rs1[256], rq1[256];
    float s0 = 0.f, q0 = 0.f, s1 = 0.f, q1 = 0.f;
    int cA = 2 * c2, cB = 2 * c2 + 1;
    if (b == 0) {
        for (int n = threadIdx.x; n < NN; n += 256) {
            float v0 = g_H[0][cA * NN + n] + g_H[1][cA * NN + n];
            float v1 = g_H[0][cB * NN + n] + g_H[1][cB * NN + n];
            row0[n] = v0; s0 += v0; q0 += v0 * v0;
            row1[n] = v1; s1 += v1; q1 += v1 * v1;
        }
    } else {
        for (int n = threadIdx.x; n < NN; n += 256) {
            float v0 = g_P[0][cA * NN + n] + g_P[1][cA * NN + n] + g_P[2][cA * NN + n] + g_P[3][cA * NN + n];
            float v1 = g_P[0][cB * NN + n] + g_P[1][cB * NN + n] + g_P[2][cB * NN + n] + g_P[3][cB * NN + n];
            row0[n] = v0; s0 += v0; q0 += v0 * v0;
            row1[n] = v1; s1 += v1; q1 += v1 * v1;
        }
    }
    rs0[threadIdx.x] = s0; rq0[threadIdx.x] = q0;
    rs1[threadIdx.x] = s1; rq1[threadIdx.x] = q1;
    __syncthreads();
    for (int o = 128; o > 0; o >>= 1) {
        if (threadIdx.x < o) {
            rs0[threadIdx.x] += rs0[threadIdx.x + o]; rq0[threadIdx.x] += rq0[threadIdx.x + o];
            rs1[threadIdx.x] += rs1[threadIdx.x + o]; rq1[threadIdx.x] += rq1[threadIdx.x + o];
        }
        __syncthreads();
    }
    float m0 = rs0[0] * (1.f / NN), m1 = rs1[0] * (1.f / NN);
    float r0 = rsqrtf(rq0[0] * (1.f / NN) - m0 * m0 + 1e-5f);
    float r1 = rsqrtf(rq1[0] * (1.f / NN) - m1 * m1 + 1e-5f);
    uint32_t* y = &g_Yp[b][c2 * XROW + 4];
    for (int n = threadIdx.x; n < NN; n += 256)
        y[n] = pk(fmaxf((row0[n] - m0) * r0, 0.f), fmaxf((row1[n] - m1) * r1, 0.f));
}

// ---------------- transposed conv (bf16, double-buffered) ----------------
__global__ void __launch_bounds__(256) k_convT_mma(int layer) {
    extern __shared__ uint32_t dyn[];
    const int n0 = blockIdx.x * 256;
    const int mt = blockIdx.y;
    const int b = blockIdx.z >> 2, q = blockIdx.z & 3;
    const int lb = layer * 2 + b;
    const int tid = threadIdx.x, lane = tid & 31, wrp = tid >> 5;
    const int wn0 = wrp * 32;
    const uint32_t smem_base = (uint32_t)__cvta_generic_to_shared(dyn);
    const uint32_t* yb = g_Yp[b] + n0;

    auto issue = [&](int cc, int s) {
        int chunk = q * 4 + cc;
        int c2b = chunk * 8;
        uint32_t ys0 = smem_base + (s * 2112) * 4;
        for (int t = tid; t < 528; t += 256) {
            int row = t / 66, qq = t - row * 66;
            cp16(ys0 + (row * 264 + qq * 4) * 4, yb + (c2b + row) * XROW + qq * 4);
        }
        const uint32_t* wsrc = g_Wt + ((size_t)((lb * 4 + mt) * 16 + chunk)) * 2304;
        uint32_t as0 = smem_base + (4224 + s * 2304) * 4;
        for (int t = tid; t < 576; t += 256)
            cp16(as0 + t * 16, wsrc + t * 4);
    };

    float acc[2][4][4] = {};
    issue(0, 0); cp_commit();
    for (int cc = 0; cc < 4; ++cc) {
        int s = cc & 1;
        if (cc < 3) { issue(cc + 1, s ^ 1); cp_commit(); cp_wait1(); }
        else cp_wait0();
        __syncthreads();
        const uint32_t* YsS = dyn + s * 2112;
        const uint32_t* AsmS = dyn + 4224 + s * 2304;
        const int r0 = (lane & 3) * 264, r1 = r0 + 4 * 264;
#pragma unroll
        for (int j = 0; j < 9; ++j) {
            uint32_t a0[4], a1[4];
            *(uint4*)a0 = *(const uint4*)&AsmS[(j * 2 + 0) * 128 + lane * 4];
            *(uint4*)a1 = *(const uint4*)&AsmS[(j * 2 + 1) * 128 + lane * 4];
            int tb = wn0 + (lane >> 2) + (8 - j);
#pragma unroll
            for (int nf = 0; nf < 4; ++nf) {
                uint32_t bb[2];
                bb[0] = YsS[r0 + tb + nf * 8];
                bb[1] = YsS[r1 + tb + nf * 8];
                mma16(acc[0][nf], a0, bb);
                mma16(acc[1][nf], a1, bb);
            }
        }
        __syncthreads();
    }
    float* T = g_T[b * 4 + q];
    const int m0 = mt * 32;
#pragma unroll
    for (int mf = 0; mf < 2; ++mf)
#pragma unroll
        for (int nf = 0; nf < 4; ++nf) {
            int m = m0 + mf * 16 + (lane >> 2);
            int n = n0 + wn0 + nf * 8 + (lane & 3) * 2;
            *(float2*)&T[m * NN + n] = make_float2(acc[mf][nf][0], acc[mf][nf][1]);
            *(float2*)&T[(m + 8) * NN + n] = make_float2(acc[mf][nf][2], acc[mf][nf][3]);
        }
}

// ---------------- GEMM: Q[kq] = T1 @ L (bf16, double-buffered) ----------------
__global__ void __launch_bounds__(256) k_gemmQ_mma() {
    extern __shared__ uint32_t dyn[];
    const int n0 = blockIdx.x * 256;
    const int m0 = blockIdx.y * 32;
    const int kq = blockIdx.z;  // 0..7
    const int tid = threadIdx.x, lane = tid & 31, wrp = tid >> 5;
    const uint32_t smem_base = (uint32_t)__cvta_generic_to_shared(dyn);

    auto prefA = [&](int cc, float* rv) {
        int k0 = kq * 128 + cc * 32;
#pragma unroll
        for (int u = 0; u < 2; ++u) {
            int idx = tid + u * 256;
            int r = idx & 3, ln = (idx >> 2) & 31, mf = (idx >> 7) & 1, kg = idx >> 8;
            int m = m0 + mf * 16 + (r & 1) * 8 + (ln >> 2);
            int k = k0 + kg * 16 + ((r >> 1) & 1) * 8 + 2 * (ln & 3);
            int off = m * NN + k;
            rv[u * 2] = g_T[4][off] + g_T[5][off] + g_T[6][off] + g_T[7][off];
            rv[u * 2 + 1] = g_T[4][off + 1] + g_T[5][off + 1] + g_T[6][off + 1] + g_T[7][off + 1];
        }
    };
    auto stA = [&](int s, const float* rv) {
#pragma unroll
        for (int u = 0; u < 2; ++u)
            dyn[s * 512 + tid + u * 256] = pk(rv[u * 2], rv[u * 2 + 1]);
    };
    auto issueB = [&](int cc, int s) {
        int kgb = kq * 8 + cc * 2;
        uint32_t bs0 = smem_base + (1024 + s * 4096) * 4;
        for (int t = tid; t < 1024; t += 256) {
            int kg = t >> 9, r = t & 511;
            cp16(bs0 + (kg * 2048 + r * 4) * 4,
                 g_Lfm + ((size_t)(kgb + kg) * 128 + (n0 >> 3)) * 64 + r * 4);
        }
    };

    float acc[2][4][4] = {};
    float rv[4], rv2[4];
    prefA(0, rv);
    issueB(0, 0); cp_commit();
    for (int cc = 0; cc < 4; ++cc) {
        int s = cc & 1;
        stA(s, rv);
        if (cc < 3) {
            issueB(cc + 1, s ^ 1); cp_commit();
            prefA(cc + 1, rv2);
            cp_wait1();
        } else cp_wait0();
        __syncthreads();
        const uint32_t* AsS = dyn + s * 512;
        const uint32_t* BsS = dyn + 1024 + s * 4096;
#pragma unroll
        for (int kg = 0; kg < 2; ++kg) {
            uint32_t a0[4], a1[4];
            *(uint4*)a0 = *(const uint4*)&AsS[(kg * 2 + 0) * 128 + lane * 4];
            *(uint4*)a1 = *(const uint4*)&AsS[(kg * 2 + 1) * 128 + lane * 4];
#pragma unroll
            for (int nf = 0; nf < 4; ++nf) {
                uint32_t bb[2];
                *(uint2*)bb = *(const uint2*)&BsS[kg * 2048 + (wrp * 4 + nf) * 64 + lane * 2];
                mma16(acc[0][nf], a0, bb);
                mma16(acc[1][nf], a1, bb);
            }
        }
        __syncthreads();
#pragma unroll
        for (int u = 0; u < 4; ++u) rv[u] = rv2[u];
    }
    float* Q = g_Q[kq];
#pragma unroll
    for (int mf = 0; mf < 2; ++mf)
#pragma unroll
        for (int nf = 0; nf < 4; ++nf) {
            int m = m0 + mf * 16 + (lane >> 2);
            int n = n0 + wrp * 32 + nf * 8 + (lane & 3) * 2;
            *(float2*)&Q[m * NN + n] = make_float2(acc[mf][nf][0], acc[mf][nf][1]);
            *(float2*)&Q[(m + 8) * NN + n] = make_float2(acc[mf][nf][2], acc[mf][nf][3]);
        }
}

// ---------------- leapfrog update + packed next-layer X ----------------
__global__ void __launch_bounds__(256) k_update(const float* __restrict__ Bias, int layer) {
    int idx = blockIdx.x * 256 + threadIdx.x;   // grid 64 -> 16384 threads
    int c2 = idx >> 8, nb = (idx & 255) * 4;
    float zn[2][4];
#pragma unroll
    for (int h = 0; h < 2; ++h) {
        int base = (2 * c2 + h) * NN + nb;
        float4 a0 = *(const float4*)&g_T[0][base];
        float4 a1 = *(const float4*)&g_T[1][base];
        float4 a2 = *(const float4*)&g_T[2][base];
        float4 a3 = *(const float4*)&g_T[3][base];
        float sx = a0.x + a1.x + a2.x + a3.x;
        float sy = a0.y + a1.y + a2.y + a3.y;
        float sz = a0.z + a1.z + a2.z + a3.z;
        float sw = a0.w + a1.w + a2.w + a3.w;
#pragma unroll
        for (int qq = 0; qq < 8; ++qq) {
            float4 t = *(const float4*)&g_Q[qq][base];
            sx += t.x; sy += t.y; sz += t.z; sw += t.w;
        }
        float4 zc = *(const float4*)&g_Zc[base];
        float4 zo = *(const float4*)&g_Zold[base];
        zn[h][0] = 2.f * zc.x - zo.x - 0.01f * sx;
        zn[h][1] = 2.f * zc.y - zo.y - 0.01f * sy;
        zn[h][2] = 2.f * zc.z - zo.z - 0.01f * sz;
        zn[h][3] = 2.f * zc.w - zo.w - 0.01f * sw;
        *(float4*)&g_Zold[base] = zc;
        *(float4*)&g_Zc[base] = *(float4*)zn[h];
    }
    if (layer + 1 < NLAYERS) {
        float b0A = Bias[((layer + 1) * 2 + 0) * NOPEN + 2 * c2];
        float b0B = Bias[((layer + 1) * 2 + 0) * NOPEN + 2 * c2 + 1];
        float b1A = Bias[((layer + 1) * 2 + 1) * NOPEN + 2 * c2];
        float b1B = Bias[((layer + 1) * 2 + 1) * NOPEN + 2 * c2 + 1];
        uint4 x0, x1;
        uint32_t* p0 = (uint32_t*)&x0;
        uint32_t* p1 = (uint32_t*)&x1;
#pragma unroll
        for (int i = 0; i < 4; ++i) {
            p0[i] = pk(zn[0][i] + b0A, zn[1][i] + b0B);
            p1[i] = pk(zn[0][i] + b1A, zn[1][i] + b1B);
        }
        *(uint4*)&g_Xp[0][c2 * XROW + 4 + nb] = x0;
        *(uint4*)&g_Xp[1][c2 * XROW + 4 + nb] = x1;
    }
}

// ---------------- output ----------------
__global__ void __launch_bounds__(256) k_out(const float* __restrict__ Kclose,
                                             float* __restrict__ out) {
    int r = blockIdx.x % 3, sel = blockIdx.x / 3;
    const float* src = sel ? g_Zold : g_Zc;
    __shared__ float kc[NOPEN];
    if (threadIdx.x < NOPEN) kc[threadIdx.x] = Kclose[r * NOPEN + threadIdx.x];
    __syncthreads();
    for (int n = threadIdx.x; n < NN; n += 256) {
        float s = 0.f;
#pragma unroll 8
        for (int k = 0; k < NOPEN; k++) s += kc[k] * src[k * NN + n];
        out[sel * (NCLOSE * NN) + r * NN + n] = s;
    }
}

// ---------------- host ----------------
extern "C" void kernel_launch(void* const* d_in, const int* in_sizes, int n_in,
                              void* d_out, int out_size) {
    const float* Z      = (const float*)d_in[0];
    const float* Kopen  = (const float*)d_in[1];
    const float* Kclose = (const float*)d_in[2];
    const float* W      = (const float*)d_in[3];
    const float* Bias   = (const float*)d_in[4];
    float* out = (float*)d_out;

    const int SM_CONV = 35328, SM_GEMM = 36864;
    cudaFuncSetAttribute(k_conv_mma, cudaFuncAttributeMaxDynamicSharedMemorySize, SM_CONV);
    cudaFuncSetAttribute(k_convT_mma, cudaFuncAttributeMaxDynamicSharedMemorySize, SM_CONV);
    cudaFuncSetAttribute(k_gemmHL_mma, cudaFuncAttributeMaxDynamicSharedMemorySize, SM_GEMM);
    cudaFuncSetAttribute(k_gemmQ_mma, cudaFuncAttributeMaxDynamicSharedMemorySize, SM_GEMM);

    k_wfmt_conv<<<5120, 256>>>(W);        // launch 0
    k_wfmt_convT<<<5120, 256>>>(W);       // 1
    k_init<<<64, 256>>>(Z, Kopen, Bias);  // 2
    for (int i = 0; i < NLAYERS; i++) {
        k_conv_mma<<<dim3(4, 8, 4), 256, SM_CONV>>>(i);   // layer0: launch 3 <- profiled
        if (i % 10 == 0) {
            k_sq<<<16, 256>>>();
            k_d2<<<dim3(16, 16), 256>>>();
            k_sigma<<<1, 256>>>();
            k_wg<<<1024, 256>>>();
            k_lap<<<1024, 256>>>();
            k_lapfm<<<1024, 256>>>();
        }
        k_gemmHL_mma<<<dim3(4, 8, 4), 256, SM_GEMM>>>();
        k_statsY<<<256, 256>>>();
        k_convT_mma<<<dim3(4, 4, 8), 256, SM_CONV>>>(i);
        k_gemmQ_mma<<<dim3(4, 4, 8), 256, SM_GEMM>>>();
        k_update<<<64, 256>>>(Bias, i);
    }
    k_out<<<6, 256>>>(Kclose, out);
}